// round 9
// baseline (speedup 1.0000x reference)
#include <cuda_runtime.h>
#include <cuda_fp16.h>
#include <math.h>
#include <stdint.h>

#define NN   20000
#define EE   320000
#define TT   16
#define PP   4096
#define DIN  128
#define HH   256
#define DDm  512
#define FFD  2048
#define TPR  (TT*PP)   // 65536
#define MB   (TT*NN)   // 320000 batched rows

// ---------------- scratch (static device globals; no allocation) ----------------
__device__ int   g_cnt   [2*MB];
__device__ int   g_rowptr[2*MB];
__device__ int   g_cursor[2*MB];
__device__ int   g_eidx  [2*TT*EE];
__device__ __half g_xh  [(size_t)2*MB*DIN];
__device__ __half g_h1h [(size_t)2*MB*HH];
__device__ __half g_aggH[(size_t)2*MB*HH];
__device__ float g_h1B [(size_t)2*MB*HH];
__device__ float g_h2B [(size_t)2*MB*HH];
__device__ float g_h   [(size_t)TPR*DDm];
__device__ float g_qkv [(size_t)TPR*1536];
__device__ float g_o   [(size_t)TPR*DDm];
__device__ float g_proj[(size_t)TPR*DDm];
__device__ float g_ff  [(size_t)TPR*FFD];
__device__ float g_bqkv[2*1536];
__device__ __half g_w[6488064];

// ---------------- helpers ----------------
__device__ __forceinline__ uint32_t smem_u32(const void* p) {
    uint32_t a;
    asm("{ .reg .u64 t; cvta.to.shared.u64 t, %1; cvt.u32.u64 %0, t; }" : "=r"(a) : "l"(p));
    return a;
}
__device__ __forceinline__ void ldsm4(uint32_t* r, uint32_t addr) {
    asm volatile("ldmatrix.sync.aligned.m8n8.x4.shared.b16 {%0,%1,%2,%3}, [%4];"
                 : "=r"(r[0]), "=r"(r[1]), "=r"(r[2]), "=r"(r[3]) : "r"(addr));
}
__device__ __forceinline__ void mma16816(float* c, const uint32_t* a, const uint32_t* b) {
    asm volatile("mma.sync.aligned.m16n8k16.row.col.f32.f16.f16.f32 "
                 "{%0,%1,%2,%3}, {%4,%5,%6,%7}, {%8,%9}, {%0,%1,%2,%3};"
                 : "+f"(c[0]), "+f"(c[1]), "+f"(c[2]), "+f"(c[3])
                 : "r"(a[0]), "r"(a[1]), "r"(a[2]), "r"(a[3]), "r"(b[0]), "r"(b[1]));
}
__device__ __forceinline__ uint32_t packh2(float a, float b) {
    __half2 t = __floats2half2_rn(a, b);
    return *reinterpret_cast<uint32_t*>(&t);
}

// smem geometry: rows of 32 fp16 padded to 80 bytes (conflict-free ldmatrix)
#define RSTR  80
#define MATB  (128*RSTR)
#define BUFB  (3*MATB)     // Ah, Al, Bh
#define GSMEM (2*BUFB)     // double buffered = 61440

// ---------------- HMMA GEMM: C = A1@W1 (+ A2h@W2) + bias, opt ReLU ------
// A1 fp32 [M][K1] split on-the-fly to fp16 hi+lo (2 products).
// A2h fp16 [M][K2] direct (1 product — exact in fp16).
// W pre-converted fp16 [N][K]. fp32 accum. Optional fp16 copy of C via Ch.
template<bool RELU>
__global__ void __launch_bounds__(256)
gemm_mma(const float* __restrict__ A1, const __half* __restrict__ B1h, int K1,
         const __half* __restrict__ A2h, const __half* __restrict__ B2h, int K2,
         const float* __restrict__ bias, float* __restrict__ C,
         __half* __restrict__ Ch, int M, int N) {
    extern __shared__ char smb[];
    const uint32_t sb = smem_u32(smb);
    const int tid = threadIdx.x, lane = tid & 31, wid = tid >> 5;
    const int bRow = blockIdx.y * 128, bCol = blockIdx.x * 128;
    const int wm = wid & 3, wn = wid >> 2;
    const int lrow = tid >> 1, lhalf = tid & 1;

    const int nc1 = K1 >> 5;
    const int nc  = nc1 + (K2 >> 5);

    float acc[2][8][4];
#pragma unroll
    for (int i = 0; i < 2; i++)
#pragma unroll
        for (int j = 0; j < 8; j++)
#pragma unroll
            for (int q = 0; q < 4; q++) acc[i][j][q] = 0.f;

    float a_st[16];
    uint4 a16_st[2];
    uint4 bh_st[2];

#define GLOAD(cc) do {                                                          \
    const int grow_ = bRow + lrow;                                              \
    if ((cc) < nc1) {                                                           \
        const int k0_ = (cc) << 5;                                              \
        if (grow_ < M) {                                                        \
            const float* ap_ = A1 + (size_t)grow_ * K1 + k0_ + lhalf * 16;      \
            *(float4*)(a_st + 0)  = ((const float4*)ap_)[0];                    \
            *(float4*)(a_st + 4)  = ((const float4*)ap_)[1];                    \
            *(float4*)(a_st + 8)  = ((const float4*)ap_)[2];                    \
            *(float4*)(a_st + 12) = ((const float4*)ap_)[3];                    \
        } else {                                                                \
            _Pragma("unroll") for (int j_ = 0; j_ < 16; j_++) a_st[j_] = 0.f;   \
        }                                                                       \
        const size_t bo_ = (size_t)(bCol + lrow) * K1 + k0_ + lhalf * 16;       \
        bh_st[0] = ((const uint4*)(B1h + bo_))[0];                              \
        bh_st[1] = ((const uint4*)(B1h + bo_))[1];                              \
    } else {                                                                    \
        const int k0_ = ((cc) - nc1) << 5;                                      \
        if (grow_ < M) {                                                        \
            const __half* ap_ = A2h + (size_t)grow_ * K2 + k0_ + lhalf * 16;    \
            a16_st[0] = ((const uint4*)ap_)[0];                                 \
            a16_st[1] = ((const uint4*)ap_)[1];                                 \
        } else {                                                                \
            a16_st[0] = make_uint4(0,0,0,0); a16_st[1] = make_uint4(0,0,0,0);   \
        }                                                                       \
        const size_t bo_ = (size_t)(bCol + lrow) * K2 + k0_ + lhalf * 16;       \
        bh_st[0] = ((const uint4*)(B2h + bo_))[0];                              \
        bh_st[1] = ((const uint4*)(B2h + bo_))[1];                              \
    }                                                                           \
} while (0)

#define SSTORE(buf, is2) do {                                                   \
    char* base_ = smb + (buf) * BUFB;                                          \
    const uint32_t ro_ = lrow * RSTR + lhalf * 32;                              \
    if (!(is2)) {                                                               \
        uint32_t hi_[8], lo_[8];                                                \
        _Pragma("unroll") for (int j_ = 0; j_ < 8; j_++) {                      \
            float f0_ = a_st[2*j_], f1_ = a_st[2*j_+1];                         \
            __half h0_ = __float2half_rn(f0_), h1_ = __float2half_rn(f1_);      \
            float v0_ = __half2float(h0_), v1_ = __half2float(h1_);             \
            hi_[j_] = packh2(v0_, v1_);                                         \
            lo_[j_] = packh2(f0_ - v0_, f1_ - v1_);                             \
        }                                                                       \
        *(uint4*)(base_ + ro_)             = make_uint4(hi_[0],hi_[1],hi_[2],hi_[3]);\
        *(uint4*)(base_ + ro_ + 16)        = make_uint4(hi_[4],hi_[5],hi_[6],hi_[7]);\
        *(uint4*)(base_ + MATB + ro_)      = make_uint4(lo_[0],lo_[1],lo_[2],lo_[3]);\
        *(uint4*)(base_ + MATB + ro_ + 16) = make_uint4(lo_[4],lo_[5],lo_[6],lo_[7]);\
    } else {                                                                    \
        *(uint4*)(base_ + ro_)      = a16_st[0];                                \
        *(uint4*)(base_ + ro_ + 16) = a16_st[1];                                \
    }                                                                           \
    *(uint4*)(base_ + 2*MATB + ro_)      = bh_st[0];                            \
    *(uint4*)(base_ + 2*MATB + ro_ + 16) = bh_st[1];                            \
} while (0)

#define COMPUTE(buf, is2) do {                                                  \
    const uint32_t ah_ = sb + (buf) * BUFB;                                     \
    const uint32_t al_ = ah_ + MATB, bhp_ = ah_ + 2*MATB;                       \
    _Pragma("unroll") for (int ks_ = 0; ks_ < 2; ks_++) {                       \
        uint32_t aH_[2][4], aL_[2][4], bH_[4][4];                               \
        const int arow_ = wm * 32 + (lane & 15);                                \
        const int acol_ = ks_ * 32 + ((lane >> 4) << 4);                        \
        ldsm4(aH_[0], ah_ + arow_ * RSTR + acol_);                              \
        ldsm4(aH_[1], ah_ + (arow_ + 16) * RSTR + acol_);                       \
        if (!(is2)) {                                                           \
            ldsm4(aL_[0], al_ + arow_ * RSTR + acol_);                          \
            ldsm4(aL_[1], al_ + (arow_ + 16) * RSTR + acol_);                   \
        }                                                                       \
        const int br_ = lane & 7, bg_ = lane >> 3;                              \
        const int brow_ = wn * 64 + ((bg_ >> 1) << 3) + br_;                    \
        const int bcol_ = ks_ * 32 + ((bg_ & 1) << 4);                          \
        _Pragma("unroll") for (int nj_ = 0; nj_ < 4; nj_++) {                   \
            ldsm4(bH_[nj_], bhp_ + (brow_ + nj_ * 16) * RSTR + bcol_);          \
        }                                                                       \
        _Pragma("unroll") for (int mi_ = 0; mi_ < 2; mi_++)                     \
        _Pragma("unroll") for (int ni_ = 0; ni_ < 8; ni_++) {                   \
            const uint32_t* bh2_ = &bH_[ni_ >> 1][(ni_ & 1) * 2];               \
            mma16816(acc[mi_][ni_], aH_[mi_], bh2_);                            \
            if (!(is2)) mma16816(acc[mi_][ni_], aL_[mi_], bh2_);                \
        }                                                                       \
    }                                                                           \
} while (0)

    GLOAD(0);
    SSTORE(0, 0 >= nc1);
    __syncthreads();
    for (int c = 0; c < nc; c++) {
        if (c + 1 < nc) GLOAD(c + 1);
        COMPUTE(c & 1, c >= nc1);
        if (c + 1 < nc) SSTORE((c + 1) & 1, (c + 1) >= nc1);
        __syncthreads();
    }

#pragma unroll
    for (int mi = 0; mi < 2; mi++) {
        const int r0 = bRow + wm * 32 + mi * 16 + (lane >> 2);
#pragma unroll
        for (int ni = 0; ni < 8; ni++) {
            const int col = bCol + wn * 64 + ni * 8 + (lane & 3) * 2;
            const float b0 = bias[col], b1 = bias[col + 1];
            if (r0 < M) {
                float c0 = acc[mi][ni][0] + b0, c1 = acc[mi][ni][1] + b1;
                if (RELU) { c0 = fmaxf(c0, 0.f); c1 = fmaxf(c1, 0.f); }
                *(float2*)(C + (size_t)r0 * N + col) = make_float2(c0, c1);
                if (Ch) *(uint32_t*)(Ch + (size_t)r0 * N + col) = packh2(c0, c1);
            }
            if (r0 + 8 < M) {
                float c2 = acc[mi][ni][2] + b0, c3 = acc[mi][ni][3] + b1;
                if (RELU) { c2 = fmaxf(c2, 0.f); c3 = fmaxf(c3, 0.f); }
                *(float2*)(C + (size_t)(r0 + 8) * N + col) = make_float2(c2, c3);
                if (Ch) *(uint32_t*)(Ch + (size_t)(r0 + 8) * N + col) = packh2(c2, c3);
            }
        }
    }
#undef GLOAD
#undef SSTORE
#undef COMPUTE
}

// ---------------- weight prep: W[K][N] fp32 -> T [N][K] fp16 ----------------
__global__ void k_wprep(const float* __restrict__ W, __half* __restrict__ Th,
                        int K, int N) {
    __shared__ float s[32][33];
    int n0 = blockIdx.x * 32, k0 = blockIdx.y * 32;
    for (int r = threadIdx.y; r < 32; r += 8)
        s[r][threadIdx.x] = W[(size_t)(k0 + r) * N + n0 + threadIdx.x];
    __syncthreads();
    for (int r = threadIdx.y; r < 32; r += 8) {
        float f = s[threadIdx.x][r];
        Th[(size_t)(n0 + r) * K + k0 + threadIdx.x] = __float2half_rn(f);
    }
}

// ---------------- fp32 -> fp16 elementwise (8 per thread) ----------------
__global__ void k_tohalf(const float* __restrict__ x, __half* __restrict__ y, unsigned n8) {
    unsigned i = blockIdx.x * blockDim.x + threadIdx.x;
    if (i >= n8) return;
    const float4* xp = (const float4*)(x) + 2 * (size_t)i;
    float4 a = xp[0], b = xp[1];
    uint4 o;
    o.x = packh2(a.x, a.y); o.y = packh2(a.z, a.w);
    o.z = packh2(b.x, b.y); o.w = packh2(b.z, b.w);
    ((uint4*)y)[i] = o;
}

// ---------------- CSR build ----------------
__global__ void k_zeroi(int* __restrict__ p, unsigned n) {
    unsigned i = blockIdx.x * blockDim.x + threadIdx.x;
    if (i < n) p[i] = 0;
}
__global__ void k_count(const int* __restrict__ dst, int* __restrict__ cnt) {
    unsigned e = blockIdx.x * blockDim.x + threadIdx.x;
    if (e >= TT * EE) return;
    int t = e / EE;
    atomicAdd(&cnt[t * NN + dst[e]], 1);
}
__global__ void k_scan(const int* __restrict__ cnt, int* __restrict__ rowptr,
                       int* __restrict__ cursor) {
    int t = blockIdx.x;
    __shared__ int sdata[1024];
    __shared__ int carry_s;
    if (threadIdx.x == 0) carry_s = t * EE;
    __syncthreads();
    for (int c0 = 0; c0 < NN; c0 += 1024) {
        int i = c0 + threadIdx.x;
        int v = (i < NN) ? cnt[t * NN + i] : 0;
        sdata[threadIdx.x] = v;
        __syncthreads();
        for (int off = 1; off < 1024; off <<= 1) {
            int add = (threadIdx.x >= (unsigned)off) ? sdata[threadIdx.x - off] : 0;
            __syncthreads();
            sdata[threadIdx.x] += add;
            __syncthreads();
        }
        int excl = sdata[threadIdx.x] - v;
        if (i < NN) {
            int r = carry_s + excl;
            rowptr[t * NN + i] = r;
            cursor[t * NN + i] = r;
        }
        __syncthreads();
        if (threadIdx.x == 0) carry_s += sdata[1023];
        __syncthreads();
    }
}
__global__ void k_fill(const int* __restrict__ src, const int* __restrict__ dst,
                       int* __restrict__ cursor, int* __restrict__ eidx) {
    unsigned e = blockIdx.x * blockDim.x + threadIdx.x;
    if (e >= TT * EE) return;
    int t = e / EE;
    int pos = atomicAdd(&cursor[t * NN + dst[e]], 1);
    eidx[pos] = t * NN + src[e];
}
// CSR mean-aggregate (fp16 in, fp32 accum, fp16 out): warp per node; F = HPL*32 halfs
template<int HPL>
__global__ void k_aggh(const __half* __restrict__ x, const int* __restrict__ rowptr,
                       const int* __restrict__ cnt, const int* __restrict__ eidx,
                       __half* __restrict__ agg) {
    int w = threadIdx.x >> 5, lane = threadIdx.x & 31;
    unsigned n = blockIdx.x * 8 + w;
    if (n >= MB) return;
    const int F = HPL * 32;
    int beg = rowptr[n], c = cnt[n];
    float acc[HPL];
#pragma unroll
    for (int j = 0; j < HPL; j++) acc[j] = 0.f;
    for (int i = 0; i < c; i++) {
        int s = eidx[beg + i];
        const __half2* r = (const __half2*)(x + (size_t)s * F + lane * HPL);
#pragma unroll
        for (int j = 0; j < HPL / 2; j++) {
            float2 f = __half22float2(r[j]);
            acc[2*j]   += f.x;
            acc[2*j+1] += f.y;
        }
    }
    float sc = 1.0f / (float)(c > 0 ? c : 1);
    uint32_t outw[HPL / 2];
#pragma unroll
    for (int j = 0; j < HPL / 2; j++)
        outw[j] = packh2(acc[2*j] * sc, acc[2*j+1] * sc);
    uint32_t* dst = (uint32_t*)(agg + (size_t)n * F + lane * HPL);
#pragma unroll
    for (int j = 0; j < HPL / 2; j++) dst[j] = outw[j];
}

// ---------------- misc kernels ----------------
__global__ void k_normgather(const float* __restrict__ h2, const int* __restrict__ idx,
                             float* __restrict__ att_out, float* __restrict__ hbuf, int off) {
    int w = threadIdx.x >> 5, lane = threadIdx.x & 31;
    unsigned tp = blockIdx.x * 8 + w;
    int t = tp >> 12, p = tp & 4095;
    int n = idx[t * PP + p];
    const float* row = h2 + ((size_t)t * NN + n) * HH;
    float v[8]; float ss = 0.f;
#pragma unroll
    for (int i = 0; i < 8; i++) { v[i] = row[lane + i * 32]; ss += v[i] * v[i]; }
#pragma unroll
    for (int o = 16; o; o >>= 1) ss += __shfl_xor_sync(0xffffffffu, ss, o);
    float inv = 1.0f / fmaxf(sqrtf(ss), 1e-12f);
    size_t o0 = (size_t)tp * DDm + off;
#pragma unroll
    for (int i = 0; i < 8; i++) {
        float val = v[i] * inv;
        att_out[o0 + lane + i * 32] = val;
        hbuf[o0 + lane + i * 32] = val;
    }
}
__global__ void k_attn(const float* __restrict__ qkv) {
    int p = blockIdx.x, h = blockIdx.y;
    int tid = threadIdx.x;
    __shared__ float qs[TT][64], ks[TT][64], vs[TT][64];
    __shared__ float att[TT][4];
    size_t base = (size_t)p * 1536 + h * 64 + tid;
#pragma unroll
    for (int t = 0; t < TT; t++) {
        size_t off = (size_t)t * PP * 1536 + base;
        qs[t][tid] = qkv[off];
        ks[t][tid] = qkv[off + 512];
        vs[t][tid] = qkv[off + 1024];
    }
    __syncthreads();
    {
        int t = tid >> 2, j = tid & 3, s = t - j;
        float sc = -INFINITY;
        if (s >= 0) {
            float a = 0.f;
#pragma unroll
            for (int d = 0; d < 64; d++) a += qs[t][d] * ks[s][d];
            sc = a * 0.125f;
        }
        att[t][j] = sc;
    }
    __syncthreads();
    if (tid < TT) {
        float m = -INFINITY;
#pragma unroll
        for (int j = 0; j < 4; j++) m = fmaxf(m, att[tid][j]);
        float sum = 0.f, e[4];
#pragma unroll
        for (int j = 0; j < 4; j++) {
            float x = att[tid][j];
            float ee = (x == -INFINITY) ? 0.f : expf(x - m);
            e[j] = ee; sum += ee;
        }
        float inv = 1.0f / sum;
#pragma unroll
        for (int j = 0; j < 4; j++) att[tid][j] = e[j] * inv;
    }
    __syncthreads();
    size_t obase = (size_t)p * DDm + h * 64 + tid;
#pragma unroll
    for (int t = 0; t < TT; t++) {
        float a = 0.f;
#pragma unroll
        for (int j = 0; j < 4; j++) {
            int s = t - j;
            if (s >= 0) a += att[t][j] * vs[s][tid];
        }
        g_o[(size_t)t * PP * DDm + obase] = a;
    }
}
__global__ void k_ln(const float* __restrict__ r, const float* __restrict__ g,
                     const float* __restrict__ b) {
    int w = threadIdx.x >> 5, lane = threadIdx.x & 31;
    size_t row = (size_t)blockIdx.x * 8 + w;
    float* xr = g_h + row * DDm;
    const float* rr = r + row * DDm;
    float v[16]; float s = 0.f;
#pragma unroll
    for (int i = 0; i < 16; i++) {
        int c = lane + i * 32;
        float t = xr[c] + rr[c];
        v[i] = t; s += t;
    }
#pragma unroll
    for (int o = 16; o; o >>= 1) s += __shfl_xor_sync(0xffffffffu, s, o);
    float mean = s * (1.0f / DDm);
    float vs = 0.f;
#pragma unroll
    for (int i = 0; i < 16; i++) { float d = v[i] - mean; vs += d * d; }
#pragma unroll
    for (int o = 16; o; o >>= 1) vs += __shfl_xor_sync(0xffffffffu, vs, o);
    float inv = rsqrtf(vs * (1.0f / DDm) + 1e-5f);
#pragma unroll
    for (int i = 0; i < 16; i++) {
        int c = lane + i * 32;
        xr[c] = (v[i] - mean) * inv * g[c] + b[c];
    }
}
__global__ void k_out(const float* __restrict__ wout, float* __restrict__ out) {
    int w = threadIdx.x >> 5, lane = threadIdx.x & 31;
    size_t row = (size_t)blockIdx.x * 8 + w;
    const float* hr = g_h + row * DDm;
    float s = 0.f;
#pragma unroll
    for (int i = 0; i < 16; i++) { int c = lane + i * 32; s += hr[c] * wout[c]; }
#pragma unroll
    for (int o = 16; o; o >>= 1) s += __shfl_xor_sync(0xffffffffu, s, o);
    if (lane == 0) out[row] = s;
}

// =======================================================================================
extern "C" void kernel_launch(void* const* d_in, const int* in_sizes, int n_in,
                              void* d_out, int out_size) {
    const float* x_i  = (const float*)d_in[0];
    const float* x_j  = (const float*)d_in[1];
    const int* src_i  = (const int*)d_in[2];
    const int* dst_i  = (const int*)d_in[3];
    const int* src_j  = (const int*)d_in[4];
    const int* dst_j  = (const int*)d_in[5];
    const int* idx_i  = (const int*)d_in[6];
    const int* idx_j  = (const int*)d_in[7];
    const float* W1s  = (const float*)d_in[8];
    const float* W1n  = (const float*)d_in[9];
    const float* b1   = (const float*)d_in[10];
    const float* W2s  = (const float*)d_in[11];
    const float* W2n  = (const float*)d_in[12];
    const float* b2   = (const float*)d_in[13];
    const float* Wq   = (const float*)d_in[14];
    const float* Wk   = (const float*)d_in[15];
    const float* Wv   = (const float*)d_in[16];
    const float* bq   = (const float*)d_in[17];
    const float* bk   = (const float*)d_in[18];
    const float* bv   = (const float*)d_in[19];
    const float* Wo   = (const float*)d_in[20];
    const float* bo   = (const float*)d_in[21];
    const float* Wf1  = (const float*)d_in[22];
    const float* bf1  = (const float*)d_in[23];
    const float* Wf2  = (const float*)d_in[24];
    const float* bf2  = (const float*)d_in[25];
    const float* g1   = (const float*)d_in[26];
    const float* bg1  = (const float*)d_in[27];
    const float* g2   = (const float*)d_in[28];
    const float* bg2  = (const float*)d_in[29];
    const float* Wout = (const float*)d_in[30];
    float* out = (float*)d_out;

    float *p_h1B, *p_h2B, *p_h, *p_qkv, *p_o, *p_proj, *p_ff, *p_bqkv;
    int *p_cnt, *p_rowptr, *p_cursor, *p_eidx;
    __half *p_w, *p_xh, *p_h1h, *p_aggH;
    cudaGetSymbolAddress((void**)&p_cnt,    g_cnt);
    cudaGetSymbolAddress((void**)&p_rowptr, g_rowptr);
    cudaGetSymbolAddress((void**)&p_cursor, g_cursor);
    cudaGetSymbolAddress((void**)&p_eidx,   g_eidx);
    cudaGetSymbolAddress((void**)&p_xh,     g_xh);
    cudaGetSymbolAddress((void**)&p_h1h,    g_h1h);
    cudaGetSymbolAddress((void**)&p_aggH,   g_aggH);
    cudaGetSymbolAddress((void**)&p_h1B,    g_h1B);
    cudaGetSymbolAddress((void**)&p_h2B,    g_h2B);
    cudaGetSymbolAddress((void**)&p_h,      g_h);
    cudaGetSymbolAddress((void**)&p_qkv,    g_qkv);
    cudaGetSymbolAddress((void**)&p_o,      g_o);
    cudaGetSymbolAddress((void**)&p_proj,   g_proj);
    cudaGetSymbolAddress((void**)&p_ff,     g_ff);
    cudaGetSymbolAddress((void**)&p_bqkv,   g_bqkv);
    cudaGetSymbolAddress((void**)&p_w,      g_w);

    cudaFuncSetAttribute(gemm_mma<false>, cudaFuncAttributeMaxDynamicSharedMemorySize, GSMEM);
    cudaFuncSetAttribute(gemm_mma<true>,  cudaFuncAttributeMaxDynamicSharedMemorySize, GSMEM);

    // ---- stream fork (capture-safe: event fork off the capturing default stream) ----
    cudaStream_t s1;
    cudaStreamCreate(&s1);
    cudaEvent_t evF, evW, evJ;
    cudaEventCreateWithFlags(&evF, cudaEventDisableTiming);
    cudaEventCreateWithFlags(&evW, cudaEventDisableTiming);
    cudaEventCreateWithFlags(&evJ, cudaEventDisableTiming);
    cudaEventRecord(evF, 0);
    cudaStreamWaitEvent(s1, evF, 0);

    // ---- weight prep on default stream ----
    size_t off = 0;
    auto prep = [&](const float* W, int K, int N) -> size_t {
        size_t b = off;
        k_wprep<<<dim3(N/32, K/32), dim3(32, 8)>>>(W, p_w + b, K, N);
        off += (size_t)K * N;
        return b;
    };
    size_t oW1s = prep(W1s, DIN, HH), oW1n = prep(W1n, DIN, HH);
    size_t oW2s = prep(W2s, HH, HH),  oW2n = prep(W2n, HH, HH);
    cudaEventRecord(evW, 0);   // SAGE weights ready

    size_t oQKV[2];
    for (int l = 0; l < 2; l++) {
        size_t b = off; off += (size_t)1536 * DDm;
        const size_t KN = (size_t)DDm * DDm;
        k_wprep<<<dim3(DDm/32, DDm/32), dim3(32, 8)>>>(Wq + (size_t)l*KN, p_w + b,        DDm, DDm);
        k_wprep<<<dim3(DDm/32, DDm/32), dim3(32, 8)>>>(Wk + (size_t)l*KN, p_w + b + KN,   DDm, DDm);
        k_wprep<<<dim3(DDm/32, DDm/32), dim3(32, 8)>>>(Wv + (size_t)l*KN, p_w + b + 2*KN, DDm, DDm);
        oQKV[l] = b;
    }
    size_t oWo[2], oWf1[2], oWf2[2];
    for (int l = 0; l < 2; l++) {
        oWo[l]  = prep(Wo  + (size_t)l*DDm*DDm, DDm, DDm);
        oWf1[l] = prep(Wf1 + (size_t)l*DDm*FFD, DDm, FFD);
        oWf2[l] = prep(Wf2 + (size_t)l*FFD*DDm, FFD, DDm);
    }
    auto BH = [&](size_t b) { return p_w + b; };

    for (int l = 0; l < 2; l++) {
        cudaMemcpyAsync(p_bqkv + l*1536,        bq + l*DDm, DDm*4, cudaMemcpyDeviceToDevice);
        cudaMemcpyAsync(p_bqkv + l*1536 + 512,  bk + l*DDm, DDm*4, cudaMemcpyDeviceToDevice);
        cudaMemcpyAsync(p_bqkv + l*1536 + 1024, bv + l*DDm, DDm*4, cudaMemcpyDeviceToDevice);
    }

    // ---------- GraphSAGE: two independent graph pipelines on two streams ----------
    for (int gsel = 0; gsel < 2; gsel++) {
        cudaStream_t st = gsel ? s1 : (cudaStream_t)0;
        const float* x  = gsel ? x_j   : x_i;
        const int* src  = gsel ? src_j : src_i;
        const int* dstp = gsel ? dst_j : dst_i;
        const int* idx  = gsel ? idx_j : idx_i;
        int*   cnt    = p_cnt    + (size_t)gsel * MB;
        int*   rowptr = p_rowptr + (size_t)gsel * MB;
        int*   cursor = p_cursor + (size_t)gsel * MB;
        int*   eidx   = p_eidx   + (size_t)gsel * TT * EE;
        __half* xh    = p_xh     + (size_t)gsel * MB * DIN;
        __half* h1h   = p_h1h    + (size_t)gsel * MB * HH;
        __half* aggH  = p_aggH   + (size_t)gsel * MB * HH;
        float* h1B    = p_h1B    + (size_t)gsel * MB * HH;
        float* h2B    = p_h2B    + (size_t)gsel * MB * HH;

        k_zeroi <<<(MB + 255)/256, 256, 0, st>>>(cnt, MB);
        k_count <<<(TT*EE + 255)/256, 256, 0, st>>>(dstp, cnt);
        k_scan  <<<TT, 1024, 0, st>>>(cnt, rowptr, cursor);
        k_fill  <<<(TT*EE + 255)/256, 256, 0, st>>>(src, dstp, cursor, eidx);
        k_tohalf<<<((unsigned)(MB*DIN/8) + 255)/256, 256, 0, st>>>(x, xh, (unsigned)(MB*DIN/8));
        k_aggh<4><<<(MB + 7)/8, 256, 0, st>>>(xh, rowptr, cnt, eidx, aggH);

        if (gsel == 1) cudaStreamWaitEvent(st, evW, 0);

        gemm_mma<true><<<dim3(HH/128, (MB + 127)/128), 256, GSMEM, st>>>(
            x, BH(oW1s), DIN, aggH, BH(oW1n), DIN, b1, h1B, h1h, MB, HH);

        k_aggh<8><<<(MB + 7)/8, 256, 0, st>>>(h1h, rowptr, cnt, eidx, aggH);
        gemm_mma<false><<<dim3(HH/128, (MB + 127)/128), 256, GSMEM, st>>>(
            h1B, BH(oW2s), HH, aggH, BH(oW2n), HH, b2, h2B, nullptr, MB, HH);

        k_normgather<<<TPR/8, 256, 0, st>>>(h2B, idx, out, p_h, gsel * HH);
    }
    cudaEventRecord(evJ, s1);
    cudaStreamWaitEvent(0, evJ, 0);

    // ---------- transformer (L=2) ----------
    for (int l = 0; l < 2; l++) {
        gemm_mma<false><<<dim3(1536/128, TPR/128), 256, GSMEM>>>(
            p_h, BH(oQKV[l]), DDm, nullptr, nullptr, 0,
            p_bqkv + l*1536, p_qkv, nullptr, TPR, 1536);

        k_attn<<<dim3(PP, 8), 64>>>(p_qkv);

        gemm_mma<false><<<dim3(DDm/128, TPR/128), 256, GSMEM>>>(
            p_o, BH(oWo[l]), DDm, nullptr, nullptr, 0,
            bo + l*DDm, p_proj, nullptr, TPR, DDm);
        k_ln<<<TPR/8, 256>>>(p_proj, g1 + l*DDm, bg1 + l*DDm);

        gemm_mma<true><<<dim3(FFD/128, TPR/128), 256, GSMEM>>>(
            p_h, BH(oWf1[l]), DDm, nullptr, nullptr, 0,
            bf1 + l*FFD, p_ff, nullptr, TPR, FFD);
        gemm_mma<false><<<dim3(DDm/128, TPR/128), 256, GSMEM>>>(
            p_ff, BH(oWf2[l]), FFD, nullptr, nullptr, 0,
            bf2 + l*DDm, p_proj, nullptr, TPR, DDm);
        k_ln<<<TPR/8, 256>>>(p_proj, g2 + l*DDm, bg2 + l*DDm);
    }

    k_out<<<TPR/8, 256>>>(Wout, out + (size_t)TPR * DDm);
}

// round 10
// speedup vs baseline: 1.2160x; 1.2160x over previous
#include <cuda_runtime.h>
#include <cuda_fp16.h>
#include <math.h>
#include <stdint.h>

#define NN   20000
#define EE   320000
#define TT   16
#define PP   4096
#define DIN  128
#define HH   256
#define DDm  512
#define FFD  2048
#define TPR  (TT*PP)   // 65536
#define MB   (TT*NN)   // 320000 batched rows

// ---------------- scratch (static device globals; no allocation) ----------------
__device__ int   g_cnt   [2*MB];
__device__ int   g_rowptr[2*MB];
__device__ int   g_cursor[2*MB];
__device__ int   g_eidx  [2*TT*EE];
__device__ float g_aggB[(size_t)2*MB*HH];
__device__ float g_h1B [(size_t)2*MB*HH];
__device__ float g_h2B [(size_t)2*MB*HH];
__device__ float g_h   [(size_t)TPR*DDm];
__device__ float g_qkv [(size_t)TPR*1536];
__device__ float g_o   [(size_t)TPR*DDm];
__device__ float g_proj[(size_t)TPR*DDm];
__device__ float g_ff  [(size_t)TPR*FFD];
__device__ float g_bqkv[2*1536];
__device__ __half g_w[6488064];

// ---------------- helpers ----------------
__device__ __forceinline__ uint32_t smem_u32(const void* p) {
    uint32_t a;
    asm("{ .reg .u64 t; cvta.to.shared.u64 t, %1; cvt.u32.u64 %0, t; }" : "=r"(a) : "l"(p));
    return a;
}
__device__ __forceinline__ void ldsm4(uint32_t* r, uint32_t addr) {
    asm volatile("ldmatrix.sync.aligned.m8n8.x4.shared.b16 {%0,%1,%2,%3}, [%4];"
                 : "=r"(r[0]), "=r"(r[1]), "=r"(r[2]), "=r"(r[3]) : "r"(addr));
}
__device__ __forceinline__ void mma16816(float* c, const uint32_t* a, const uint32_t* b) {
    asm volatile("mma.sync.aligned.m16n8k16.row.col.f32.f16.f16.f32 "
                 "{%0,%1,%2,%3}, {%4,%5,%6,%7}, {%8,%9}, {%0,%1,%2,%3};"
                 : "+f"(c[0]), "+f"(c[1]), "+f"(c[2]), "+f"(c[3])
                 : "r"(a[0]), "r"(a[1]), "r"(a[2]), "r"(a[3]), "r"(b[0]), "r"(b[1]));
}
__device__ __forceinline__ uint32_t packh2(float a, float b) {
    __half2 t = __floats2half2_rn(a, b);
    return *reinterpret_cast<uint32_t*>(&t);
}

// smem geometry: rows of 32 fp16 padded to 80 bytes (conflict-free ldmatrix)
#define RSTR  80
#define MATB  (128*RSTR)
#define BUFB  (3*MATB)     // Ah, Al, Bh
#define GSMEM (2*BUFB)     // double buffered = 61440

// ---------------- HMMA GEMM: C = A1@W1 (+ A2@W2) + bias, opt ReLU ------
// A fp32 [M][K] split on the fly to fp16 hi(+lo); W pre-converted fp16 [N][K].
// SINGLE1=false: two products (Ah*B + Al*B), product err ~2^-11 (B rounding).
// SINGLE1=true : one product  (Ah*B),        product err ~sqrt2*2^-11 (A+B rounding).
template<bool RELU, bool SINGLE1>
__global__ void __launch_bounds__(256)
gemm_mma(const float* __restrict__ A1, const __half* __restrict__ B1h, int K1,
         const float* __restrict__ A2, const __half* __restrict__ B2h, int K2,
         const float* __restrict__ bias, float* __restrict__ C, int M, int N) {
    extern __shared__ char smb[];
    const uint32_t sb = smem_u32(smb);
    const int tid = threadIdx.x, lane = tid & 31, wid = tid >> 5;
    const int bRow = blockIdx.y * 128, bCol = blockIdx.x * 128;
    const int wm = wid & 3, wn = wid >> 2;
    const int lrow = tid >> 1, lhalf = tid & 1;

    const int nc1 = K1 >> 5;
    const int nc  = nc1 + (K2 >> 5);

    float acc[2][8][4];
#pragma unroll
    for (int i = 0; i < 2; i++)
#pragma unroll
        for (int j = 0; j < 8; j++)
#pragma unroll
            for (int q = 0; q < 4; q++) acc[i][j][q] = 0.f;

    float a_st[16];
    uint4 bh_st[2];

#define GLOAD(cc) do {                                                          \
    const float* A_; const __half* Bh_; int K_, k0_;                            \
    if ((cc) < nc1) { A_ = A1; Bh_ = B1h; K_ = K1; k0_ = (cc) << 5; }           \
    else { A_ = A2; Bh_ = B2h; K_ = K2; k0_ = ((cc) - nc1) << 5; }              \
    const int grow_ = bRow + lrow;                                              \
    if (grow_ < M) {                                                            \
        const float* ap_ = A_ + (size_t)grow_ * K_ + k0_ + lhalf * 16;          \
        *(float4*)(a_st + 0)  = ((const float4*)ap_)[0];                        \
        *(float4*)(a_st + 4)  = ((const float4*)ap_)[1];                        \
        *(float4*)(a_st + 8)  = ((const float4*)ap_)[2];                        \
        *(float4*)(a_st + 12) = ((const float4*)ap_)[3];                        \
    } else {                                                                    \
        _Pragma("unroll") for (int j_ = 0; j_ < 16; j_++) a_st[j_] = 0.f;       \
    }                                                                           \
    const size_t bo_ = (size_t)(bCol + lrow) * K_ + k0_ + lhalf * 16;           \
    bh_st[0] = ((const uint4*)(Bh_ + bo_))[0];                                  \
    bh_st[1] = ((const uint4*)(Bh_ + bo_))[1];                                  \
} while (0)

#define SSTORE(buf) do {                                                        \
    char* base_ = smb + (buf) * BUFB;                                          \
    const uint32_t ro_ = lrow * RSTR + lhalf * 32;                              \
    uint32_t hi_[8], lo_[8];                                                    \
    _Pragma("unroll") for (int j_ = 0; j_ < 8; j_++) {                          \
        float f0_ = a_st[2*j_], f1_ = a_st[2*j_+1];                             \
        __half h0_ = __float2half_rn(f0_), h1_ = __float2half_rn(f1_);          \
        float v0_ = __half2float(h0_), v1_ = __half2float(h1_);                 \
        hi_[j_] = packh2(v0_, v1_);                                             \
        lo_[j_] = packh2(f0_ - v0_, f1_ - v1_);                                 \
    }                                                                           \
    *(uint4*)(base_ + ro_)             = make_uint4(hi_[0],hi_[1],hi_[2],hi_[3]);\
    *(uint4*)(base_ + ro_ + 16)        = make_uint4(hi_[4],hi_[5],hi_[6],hi_[7]);\
    if (!SINGLE1) {                                                             \
        *(uint4*)(base_ + MATB + ro_)      = make_uint4(lo_[0],lo_[1],lo_[2],lo_[3]);\
        *(uint4*)(base_ + MATB + ro_ + 16) = make_uint4(lo_[4],lo_[5],lo_[6],lo_[7]);\
    }                                                                           \
    *(uint4*)(base_ + 2*MATB + ro_)      = bh_st[0];                            \
    *(uint4*)(base_ + 2*MATB + ro_ + 16) = bh_st[1];                            \
} while (0)

#define COMPUTE(buf) do {                                                       \
    const uint32_t ah_ = sb + (buf) * BUFB;                                     \
    const uint32_t al_ = ah_ + MATB, bhp_ = ah_ + 2*MATB;                       \
    _Pragma("unroll") for (int ks_ = 0; ks_ < 2; ks_++) {                       \
        uint32_t aH_[2][4], aL_[2][4], bH_[4][4];                               \
        const int arow_ = wm * 32 + (lane & 15);                                \
        const int acol_ = ks_ * 32 + ((lane >> 4) << 4);                        \
        ldsm4(aH_[0], ah_ + arow_ * RSTR + acol_);                              \
        ldsm4(aH_[1], ah_ + (arow_ + 16) * RSTR + acol_);                       \
        if (!SINGLE1) {                                                         \
            ldsm4(aL_[0], al_ + arow_ * RSTR + acol_);                          \
            ldsm4(aL_[1], al_ + (arow_ + 16) * RSTR + acol_);                   \
        }                                                                       \
        const int br_ = lane & 7, bg_ = lane >> 3;                              \
        const int brow_ = wn * 64 + ((bg_ >> 1) << 3) + br_;                    \
        const int bcol_ = ks_ * 32 + ((bg_ & 1) << 4);                          \
        _Pragma("unroll") for (int nj_ = 0; nj_ < 4; nj_++) {                   \
            ldsm4(bH_[nj_], bhp_ + (brow_ + nj_ * 16) * RSTR + bcol_);          \
        }                                                                       \
        _Pragma("unroll") for (int mi_ = 0; mi_ < 2; mi_++)                     \
        _Pragma("unroll") for (int ni_ = 0; ni_ < 8; ni_++) {                   \
            const uint32_t* bh2_ = &bH_[ni_ >> 1][(ni_ & 1) * 2];               \
            mma16816(acc[mi_][ni_], aH_[mi_], bh2_);                            \
            if (!SINGLE1) mma16816(acc[mi_][ni_], aL_[mi_], bh2_);              \
        }                                                                       \
    }                                                                           \
} while (0)

    GLOAD(0);
    SSTORE(0);
    __syncthreads();
    for (int c = 0; c < nc; c++) {
        if (c + 1 < nc) GLOAD(c + 1);
        COMPUTE(c & 1);
        if (c + 1 < nc) SSTORE((c + 1) & 1);
        __syncthreads();
    }

#pragma unroll
    for (int mi = 0; mi < 2; mi++) {
        const int r0 = bRow + wm * 32 + mi * 16 + (lane >> 2);
#pragma unroll
        for (int ni = 0; ni < 8; ni++) {
            const int col = bCol + wn * 64 + ni * 8 + (lane & 3) * 2;
            const float b0 = bias[col], b1 = bias[col + 1];
            if (r0 < M) {
                float c0 = acc[mi][ni][0] + b0, c1 = acc[mi][ni][1] + b1;
                if (RELU) { c0 = fmaxf(c0, 0.f); c1 = fmaxf(c1, 0.f); }
                *(float2*)(C + (size_t)r0 * N + col) = make_float2(c0, c1);
            }
            if (r0 + 8 < M) {
                float c2 = acc[mi][ni][2] + b0, c3 = acc[mi][ni][3] + b1;
                if (RELU) { c2 = fmaxf(c2, 0.f); c3 = fmaxf(c3, 0.f); }
                *(float2*)(C + (size_t)(r0 + 8) * N + col) = make_float2(c2, c3);
            }
        }
    }
#undef GLOAD
#undef SSTORE
#undef COMPUTE
}

// ---------------- weight prep: W[K][N] fp32 -> T [N][K] fp16 ----------------
__global__ void k_wprep(const float* __restrict__ W, __half* __restrict__ Th,
                        int K, int N) {
    __shared__ float s[32][33];
    int n0 = blockIdx.x * 32, k0 = blockIdx.y * 32;
    for (int r = threadIdx.y; r < 32; r += 8)
        s[r][threadIdx.x] = W[(size_t)(k0 + r) * N + n0 + threadIdx.x];
    __syncthreads();
    for (int r = threadIdx.y; r < 32; r += 8) {
        float f = s[threadIdx.x][r];
        Th[(size_t)(n0 + r) * K + k0 + threadIdx.x] = __float2half_rn(f);
    }
}

// ---------------- CSR build ----------------
__global__ void k_zeroi(int* __restrict__ p, unsigned n) {
    unsigned i = blockIdx.x * blockDim.x + threadIdx.x;
    if (i < n) p[i] = 0;
}
__global__ void k_count(const int* __restrict__ dst, int* __restrict__ cnt) {
    unsigned e = blockIdx.x * blockDim.x + threadIdx.x;
    if (e >= TT * EE) return;
    int t = e / EE;
    atomicAdd(&cnt[t * NN + dst[e]], 1);
}
__global__ void k_scan(const int* __restrict__ cnt, int* __restrict__ rowptr,
                       int* __restrict__ cursor) {
    int t = blockIdx.x;
    __shared__ int sdata[1024];
    __shared__ int carry_s;
    if (threadIdx.x == 0) carry_s = t * EE;
    __syncthreads();
    for (int c0 = 0; c0 < NN; c0 += 1024) {
        int i = c0 + threadIdx.x;
        int v = (i < NN) ? cnt[t * NN + i] : 0;
        sdata[threadIdx.x] = v;
        __syncthreads();
        for (int off = 1; off < 1024; off <<= 1) {
            int add = (threadIdx.x >= (unsigned)off) ? sdata[threadIdx.x - off] : 0;
            __syncthreads();
            sdata[threadIdx.x] += add;
            __syncthreads();
        }
        int excl = sdata[threadIdx.x] - v;
        if (i < NN) {
            int r = carry_s + excl;
            rowptr[t * NN + i] = r;
            cursor[t * NN + i] = r;
        }
        __syncthreads();
        if (threadIdx.x == 0) carry_s += sdata[1023];
        __syncthreads();
    }
}
__global__ void k_fill(const int* __restrict__ src, const int* __restrict__ dst,
                       int* __restrict__ cursor, int* __restrict__ eidx) {
    unsigned e = blockIdx.x * blockDim.x + threadIdx.x;
    if (e >= TT * EE) return;
    int t = e / EE;
    int pos = atomicAdd(&cursor[t * NN + dst[e]], 1);
    eidx[pos] = t * NN + src[e];
}
// CSR mean-aggregate: warp per node row; F = F4PL*128 floats
template<int F4PL>
__global__ void k_agg(const float* __restrict__ x, const int* __restrict__ rowptr,
                      const int* __restrict__ cnt, const int* __restrict__ eidx,
                      float* __restrict__ agg) {
    int w = threadIdx.x >> 5, lane = threadIdx.x & 31;
    unsigned n = blockIdx.x * 8 + w;
    if (n >= MB) return;
    const int F = F4PL * 128;
    int beg = rowptr[n], c = cnt[n];
    float4 acc[F4PL];
#pragma unroll
    for (int j = 0; j < F4PL; j++) acc[j] = make_float4(0.f, 0.f, 0.f, 0.f);
    int i = 0;
    for (; i + 1 < c; i += 2) {
        int s0 = eidx[beg + i], s1 = eidx[beg + i + 1];
        const float4* r0 = (const float4*)(x + (size_t)s0 * F);
        const float4* r1 = (const float4*)(x + (size_t)s1 * F);
#pragma unroll
        for (int j = 0; j < F4PL; j++) {
            float4 a = r0[lane + 32 * j], b = r1[lane + 32 * j];
            acc[j].x += a.x + b.x; acc[j].y += a.y + b.y;
            acc[j].z += a.z + b.z; acc[j].w += a.w + b.w;
        }
    }
    if (i < c) {
        const float4* r0 = (const float4*)(x + (size_t)eidx[beg + i] * F);
#pragma unroll
        for (int j = 0; j < F4PL; j++) {
            float4 a = r0[lane + 32 * j];
            acc[j].x += a.x; acc[j].y += a.y; acc[j].z += a.z; acc[j].w += a.w;
        }
    }
    float sc = 1.0f / (float)(c > 0 ? c : 1);
    float4* dst = (float4*)(agg + (size_t)n * F);
#pragma unroll
    for (int j = 0; j < F4PL; j++) {
        acc[j].x *= sc; acc[j].y *= sc; acc[j].z *= sc; acc[j].w *= sc;
        dst[lane + 32 * j] = acc[j];
    }
}

// ---------------- misc kernels ----------------
__global__ void k_normgather(const float* __restrict__ h2, const int* __restrict__ idx,
                             float* __restrict__ att_out, float* __restrict__ hbuf, int off) {
    int w = threadIdx.x >> 5, lane = threadIdx.x & 31;
    unsigned tp = blockIdx.x * 8 + w;
    int t = tp >> 12, p = tp & 4095;
    int n = idx[t * PP + p];
    const float* row = h2 + ((size_t)t * NN + n) * HH;
    float v[8]; float ss = 0.f;
#pragma unroll
    for (int i = 0; i < 8; i++) { v[i] = row[lane + i * 32]; ss += v[i] * v[i]; }
#pragma unroll
    for (int o = 16; o; o >>= 1) ss += __shfl_xor_sync(0xffffffffu, ss, o);
    float inv = 1.0f / fmaxf(sqrtf(ss), 1e-12f);
    size_t o0 = (size_t)tp * DDm + off;
#pragma unroll
    for (int i = 0; i < 8; i++) {
        float val = v[i] * inv;
        att_out[o0 + lane + i * 32] = val;
        hbuf[o0 + lane + i * 32] = val;
    }
}
__global__ void k_attn(const float* __restrict__ qkv) {
    int p = blockIdx.x, h = blockIdx.y;
    int tid = threadIdx.x;
    __shared__ float qs[TT][64], ks[TT][64], vs[TT][64];
    __shared__ float att[TT][4];
    size_t base = (size_t)p * 1536 + h * 64 + tid;
#pragma unroll
    for (int t = 0; t < TT; t++) {
        size_t off = (size_t)t * PP * 1536 + base;
        qs[t][tid] = qkv[off];
        ks[t][tid] = qkv[off + 512];
        vs[t][tid] = qkv[off + 1024];
    }
    __syncthreads();
    {
        int t = tid >> 2, j = tid & 3, s = t - j;
        float sc = -INFINITY;
        if (s >= 0) {
            float a = 0.f;
#pragma unroll
            for (int d = 0; d < 64; d++) a += qs[t][d] * ks[s][d];
            sc = a * 0.125f;
        }
        att[t][j] = sc;
    }
    __syncthreads();
    if (tid < TT) {
        float m = -INFINITY;
#pragma unroll
        for (int j = 0; j < 4; j++) m = fmaxf(m, att[tid][j]);
        float sum = 0.f, e[4];
#pragma unroll
        for (int j = 0; j < 4; j++) {
            float x = att[tid][j];
            float ee = (x == -INFINITY) ? 0.f : expf(x - m);
            e[j] = ee; sum += ee;
        }
        float inv = 1.0f / sum;
#pragma unroll
        for (int j = 0; j < 4; j++) att[tid][j] = e[j] * inv;
    }
    __syncthreads();
    size_t obase = (size_t)p * DDm + h * 64 + tid;
#pragma unroll
    for (int t = 0; t < TT; t++) {
        float a = 0.f;
#pragma unroll
        for (int j = 0; j < 4; j++) {
            int s = t - j;
            if (s >= 0) a += att[t][j] * vs[s][tid];
        }
        g_o[(size_t)t * PP * DDm + obase] = a;
    }
}
__global__ void k_ln(const float* __restrict__ r, const float* __restrict__ g,
                     const float* __restrict__ b) {
    int w = threadIdx.x >> 5, lane = threadIdx.x & 31;
    size_t row = (size_t)blockIdx.x * 8 + w;
    float* xr = g_h + row * DDm;
    const float* rr = r + row * DDm;
    float v[16]; float s = 0.f;
#pragma unroll
    for (int i = 0; i < 16; i++) {
        int c = lane + i * 32;
        float t = xr[c] + rr[c];
        v[i] = t; s += t;
    }
#pragma unroll
    for (int o = 16; o; o >>= 1) s += __shfl_xor_sync(0xffffffffu, s, o);
    float mean = s * (1.0f / DDm);
    float vs = 0.f;
#pragma unroll
    for (int i = 0; i < 16; i++) { float d = v[i] - mean; vs += d * d; }
#pragma unroll
    for (int o = 16; o; o >>= 1) vs += __shfl_xor_sync(0xffffffffu, vs, o);
    float inv = rsqrtf(vs * (1.0f / DDm) + 1e-5f);
#pragma unroll
    for (int i = 0; i < 16; i++) {
        int c = lane + i * 32;
        xr[c] = (v[i] - mean) * inv * g[c] + b[c];
    }
}
__global__ void k_out(const float* __restrict__ wout, float* __restrict__ out) {
    int w = threadIdx.x >> 5, lane = threadIdx.x & 31;
    size_t row = (size_t)blockIdx.x * 8 + w;
    const float* hr = g_h + row * DDm;
    float s = 0.f;
#pragma unroll
    for (int i = 0; i < 16; i++) { int c = lane + i * 32; s += hr[c] * wout[c]; }
#pragma unroll
    for (int o = 16; o; o >>= 1) s += __shfl_xor_sync(0xffffffffu, s, o);
    if (lane == 0) out[row] = s;
}

// =======================================================================================
extern "C" void kernel_launch(void* const* d_in, const int* in_sizes, int n_in,
                              void* d_out, int out_size) {
    const float* x_i  = (const float*)d_in[0];
    const float* x_j  = (const float*)d_in[1];
    const int* src_i  = (const int*)d_in[2];
    const int* dst_i  = (const int*)d_in[3];
    const int* src_j  = (const int*)d_in[4];
    const int* dst_j  = (const int*)d_in[5];
    const int* idx_i  = (const int*)d_in[6];
    const int* idx_j  = (const int*)d_in[7];
    const float* W1s  = (const float*)d_in[8];
    const float* W1n  = (const float*)d_in[9];
    const float* b1   = (const float*)d_in[10];
    const float* W2s  = (const float*)d_in[11];
    const float* W2n  = (const float*)d_in[12];
    const float* b2   = (const float*)d_in[13];
    const float* Wq   = (const float*)d_in[14];
    const float* Wk   = (const float*)d_in[15];
    const float* Wv   = (const float*)d_in[16];
    const float* bq   = (const float*)d_in[17];
    const float* bk   = (const float*)d_in[18];
    const float* bv   = (const float*)d_in[19];
    const float* Wo   = (const float*)d_in[20];
    const float* bo   = (const float*)d_in[21];
    const float* Wf1  = (const float*)d_in[22];
    const float* bf1  = (const float*)d_in[23];
    const float* Wf2  = (const float*)d_in[24];
    const float* bf2  = (const float*)d_in[25];
    const float* g1   = (const float*)d_in[26];
    const float* bg1  = (const float*)d_in[27];
    const float* g2   = (const float*)d_in[28];
    const float* bg2  = (const float*)d_in[29];
    const float* Wout = (const float*)d_in[30];
    float* out = (float*)d_out;

    float *p_aggB, *p_h1B, *p_h2B, *p_h, *p_qkv, *p_o, *p_proj, *p_ff, *p_bqkv;
    int *p_cnt, *p_rowptr, *p_cursor, *p_eidx;
    __half* p_w;
    cudaGetSymbolAddress((void**)&p_cnt,    g_cnt);
    cudaGetSymbolAddress((void**)&p_rowptr, g_rowptr);
    cudaGetSymbolAddress((void**)&p_cursor, g_cursor);
    cudaGetSymbolAddress((void**)&p_eidx,   g_eidx);
    cudaGetSymbolAddress((void**)&p_aggB,   g_aggB);
    cudaGetSymbolAddress((void**)&p_h1B,    g_h1B);
    cudaGetSymbolAddress((void**)&p_h2B,    g_h2B);
    cudaGetSymbolAddress((void**)&p_h,      g_h);
    cudaGetSymbolAddress((void**)&p_qkv,    g_qkv);
    cudaGetSymbolAddress((void**)&p_o,      g_o);
    cudaGetSymbolAddress((void**)&p_proj,   g_proj);
    cudaGetSymbolAddress((void**)&p_ff,     g_ff);
    cudaGetSymbolAddress((void**)&p_bqkv,   g_bqkv);
    cudaGetSymbolAddress((void**)&p_w,      g_w);

    cudaFuncSetAttribute(gemm_mma<false,false>, cudaFuncAttributeMaxDynamicSharedMemorySize, GSMEM);
    cudaFuncSetAttribute(gemm_mma<true,false>,  cudaFuncAttributeMaxDynamicSharedMemorySize, GSMEM);
    cudaFuncSetAttribute(gemm_mma<false,true>,  cudaFuncAttributeMaxDynamicSharedMemorySize, GSMEM);
    cudaFuncSetAttribute(gemm_mma<true,true>,   cudaFuncAttributeMaxDynamicSharedMemorySize, GSMEM);

    // ---- stream fork (capture-safe: event fork off the capturing default stream) ----
    cudaStream_t s1;
    cudaStreamCreate(&s1);
    cudaEvent_t evF, evW, evJ;
    cudaEventCreateWithFlags(&evF, cudaEventDisableTiming);
    cudaEventCreateWithFlags(&evW, cudaEventDisableTiming);
    cudaEventCreateWithFlags(&evJ, cudaEventDisableTiming);
    cudaEventRecord(evF, 0);
    cudaStreamWaitEvent(s1, evF, 0);

    // ---- weight prep on default stream ----
    size_t off = 0;
    auto prep = [&](const float* W, int K, int N) -> size_t {
        size_t b = off;
        k_wprep<<<dim3(N/32, K/32), dim3(32, 8)>>>(W, p_w + b, K, N);
        off += (size_t)K * N;
        return b;
    };
    size_t oW1s = prep(W1s, DIN, HH), oW1n = prep(W1n, DIN, HH);
    size_t oW2s = prep(W2s, HH, HH),  oW2n = prep(W2n, HH, HH);
    cudaEventRecord(evW, 0);   // SAGE weights ready

    size_t oQKV[2];
    for (int l = 0; l < 2; l++) {
        size_t b = off; off += (size_t)1536 * DDm;
        const size_t KN = (size_t)DDm * DDm;
        k_wprep<<<dim3(DDm/32, DDm/32), dim3(32, 8)>>>(Wq + (size_t)l*KN, p_w + b,        DDm, DDm);
        k_wprep<<<dim3(DDm/32, DDm/32), dim3(32, 8)>>>(Wk + (size_t)l*KN, p_w + b + KN,   DDm, DDm);
        k_wprep<<<dim3(DDm/32, DDm/32), dim3(32, 8)>>>(Wv + (size_t)l*KN, p_w + b + 2*KN, DDm, DDm);
        oQKV[l] = b;
    }
    size_t oWo[2], oWf1[2], oWf2[2];
    for (int l = 0; l < 2; l++) {
        oWo[l]  = prep(Wo  + (size_t)l*DDm*DDm, DDm, DDm);
        oWf1[l] = prep(Wf1 + (size_t)l*DDm*FFD, DDm, FFD);
        oWf2[l] = prep(Wf2 + (size_t)l*FFD*DDm, FFD, DDm);
    }
    auto BH = [&](size_t b) { return p_w + b; };

    for (int l = 0; l < 2; l++) {
        cudaMemcpyAsync(p_bqkv + l*1536,        bq + l*DDm, DDm*4, cudaMemcpyDeviceToDevice);
        cudaMemcpyAsync(p_bqkv + l*1536 + 512,  bk + l*DDm, DDm*4, cudaMemcpyDeviceToDevice);
        cudaMemcpyAsync(p_bqkv + l*1536 + 1024, bv + l*DDm, DDm*4, cudaMemcpyDeviceToDevice);
    }

    // ---------- GraphSAGE: two independent graph pipelines on two streams ----------
    for (int gsel = 0; gsel < 2; gsel++) {
        cudaStream_t st = gsel ? s1 : (cudaStream_t)0;
        const float* x  = gsel ? x_j   : x_i;
        const int* src  = gsel ? src_j : src_i;
        const int* dstp = gsel ? dst_j : dst_i;
        const int* idx  = gsel ? idx_j : idx_i;
        int*   cnt    = p_cnt    + (size_t)gsel * MB;
        int*   rowptr = p_rowptr + (size_t)gsel * MB;
        int*   cursor = p_cursor + (size_t)gsel * MB;
        int*   eidx   = p_eidx   + (size_t)gsel * TT * EE;
        float* aggB   = p_aggB   + (size_t)gsel * MB * HH;
        float* h1B    = p_h1B    + (size_t)gsel * MB * HH;
        float* h2B    = p_h2B    + (size_t)gsel * MB * HH;

        k_zeroi<<<(MB + 255)/256, 256, 0, st>>>(cnt, MB);
        k_count<<<(TT*EE + 255)/256, 256, 0, st>>>(dstp, cnt);
        k_scan <<<TT, 1024, 0, st>>>(cnt, rowptr, cursor);
        k_fill <<<(TT*EE + 255)/256, 256, 0, st>>>(src, dstp, cursor, eidx);
        k_agg<1><<<(MB + 7)/8, 256, 0, st>>>(x, rowptr, cnt, eidx, aggB);

        if (gsel == 1) cudaStreamWaitEvent(st, evW, 0);

        gemm_mma<true,false><<<dim3(HH/128, (MB + 127)/128), 256, GSMEM, st>>>(
            x, BH(oW1s), DIN, aggB, BH(oW1n), DIN, b1, h1B, MB, HH);

        k_agg<2><<<(MB + 7)/8, 256, 0, st>>>(h1B, rowptr, cnt, eidx, aggB);
        gemm_mma<false,false><<<dim3(HH/128, (MB + 127)/128), 256, GSMEM, st>>>(
            h1B, BH(oW2s), HH, aggB, BH(oW2n), HH, b2, h2B, MB, HH);

        k_normgather<<<TPR/8, 256, 0, st>>>(h2B, idx, out, p_h, gsel * HH);
    }
    cudaEventRecord(evJ, s1);
    cudaStreamWaitEvent(0, evJ, 0);

    // ---------- transformer (L=2) ----------
    for (int l = 0; l < 2; l++) {
        gemm_mma<false,false><<<dim3(1536/128, TPR/128), 256, GSMEM>>>(
            p_h, BH(oQKV[l]), DDm, nullptr, nullptr, 0,
            p_bqkv + l*1536, p_qkv, TPR, 1536);

        k_attn<<<dim3(PP, 8), 64>>>(p_qkv);

        gemm_mma<false,false><<<dim3(DDm/128, TPR/128), 256, GSMEM>>>(
            p_o, BH(oWo[l]), DDm, nullptr, nullptr, 0,
            bo + l*DDm, p_proj, TPR, DDm);
        k_ln<<<TPR/8, 256>>>(p_proj, g1 + l*DDm, bg1 + l*DDm);

        // FF GEMMs: single-product fp16 (A rounded too) — halves mma count here
        gemm_mma<true,true><<<dim3(FFD/128, TPR/128), 256, GSMEM>>>(
            p_h, BH(oWf1[l]), DDm, nullptr, nullptr, 0,
            bf1 + l*FFD, p_ff, TPR, FFD);
        gemm_mma<false,true><<<dim3(DDm/128, TPR/128), 256, GSMEM>>>(
            p_ff, BH(oWf2[l]), FFD, nullptr, nullptr, 0,
            bf2 + l*DDm, p_proj, TPR, DDm);
        k_ln<<<TPR/8, 256>>>(p_proj, g2 + l*DDm, bg2 + l*DDm);
    }

    k_out<<<TPR/8, 256>>>(Wout, out + (size_t)TPR * DDm);
}

// round 11
// speedup vs baseline: 1.4264x; 1.1731x over previous
#include <cuda_runtime.h>
#include <cuda_fp16.h>
#include <math.h>
#include <stdint.h>

#define NN   20000
#define EE   320000
#define TT   16
#define PP   4096
#define DIN  128
#define HH   256
#define DDm  512
#define FFD  2048
#define TPR  (TT*PP)   // 65536
#define MB   (TT*NN)   // 320000 batched rows

// ---------------- scratch (static device globals; no allocation) ----------------
__device__ int   g_cnt   [2*MB];
__device__ int   g_rowptr[2*MB];
__device__ int   g_cursor[2*MB];
__device__ int   g_eidx  [2*TT*EE];
__device__ float g_aggB[(size_t)2*MB*HH];
__device__ float g_h1B [(size_t)2*MB*HH];
__device__ float g_h2B [(size_t)2*MB*HH];
__device__ float g_h   [(size_t)TPR*DDm];
__device__ float g_qkv [(size_t)TPR*1536];
__device__ __half g_oh [(size_t)TPR*DDm];
__device__ __half g_ffh[(size_t)TPR*FFD];
__device__ float g_proj[(size_t)TPR*DDm];
__device__ float g_bqkv[2*1536];
__device__ __half g_w[6488064];

// ---------------- helpers ----------------
__device__ __forceinline__ uint32_t smem_u32(const void* p) {
    uint32_t a;
    asm("{ .reg .u64 t; cvta.to.shared.u64 t, %1; cvt.u32.u64 %0, t; }" : "=r"(a) : "l"(p));
    return a;
}
__device__ __forceinline__ void ldsm4(uint32_t* r, uint32_t addr) {
    asm volatile("ldmatrix.sync.aligned.m8n8.x4.shared.b16 {%0,%1,%2,%3}, [%4];"
                 : "=r"(r[0]), "=r"(r[1]), "=r"(r[2]), "=r"(r[3]) : "r"(addr));
}
__device__ __forceinline__ void mma16816(float* c, const uint32_t* a, const uint32_t* b) {
    asm volatile("mma.sync.aligned.m16n8k16.row.col.f32.f16.f16.f32 "
                 "{%0,%1,%2,%3}, {%4,%5,%6,%7}, {%8,%9}, {%0,%1,%2,%3};"
                 : "+f"(c[0]), "+f"(c[1]), "+f"(c[2]), "+f"(c[3])
                 : "r"(a[0]), "r"(a[1]), "r"(a[2]), "r"(a[3]), "r"(b[0]), "r"(b[1]));
}
__device__ __forceinline__ uint32_t packh2(float a, float b) {
    __half2 t = __floats2half2_rn(a, b);
    return *reinterpret_cast<uint32_t*>(&t);
}

// smem geometry: rows of 32 fp16 padded to 80 bytes (conflict-free ldmatrix)
#define RSTR  80
#define MATB  (128*RSTR)
#define BUFB  (3*MATB)     // Ah, Al, Bh
#define GSMEM (2*BUFB)     // double buffered = 61440

// ---------------- HMMA GEMM: C = A1@W1 (+ A2@W2) + bias, opt ReLU ------
// SINGLE=false: A split to fp16 hi+lo, two products (err ~2^-11, B rounding only).
// SINGLE=true : one product, A rounded to fp16 (err ~sqrt2*2^-11).
// AHALF=true  : A1 is already fp16 (K2 must be 0); one product, no conversion.
// C (fp32) and Ch (fp16) outputs each optional.
template<bool RELU, bool SINGLE, bool AHALF>
__global__ void __launch_bounds__(256)
gemm_mma(const void* __restrict__ A1v, const __half* __restrict__ B1h, int K1,
         const float* __restrict__ A2, const __half* __restrict__ B2h, int K2,
         const float* __restrict__ bias, float* __restrict__ C,
         __half* __restrict__ Ch, int M, int N) {
    extern __shared__ char smb[];
    const uint32_t sb = smem_u32(smb);
    const int tid = threadIdx.x, lane = tid & 31, wid = tid >> 5;
    const int bRow = blockIdx.y * 128, bCol = blockIdx.x * 128;
    const int wm = wid & 3, wn = wid >> 2;
    const int lrow = tid >> 1, lhalf = tid & 1;

    const float*  A1f = (const float*)A1v;
    const __half* A1h = (const __half*)A1v;

    const int nc1 = K1 >> 5;
    const int nc  = nc1 + (K2 >> 5);

    float acc[2][8][4];
#pragma unroll
    for (int i = 0; i < 2; i++)
#pragma unroll
        for (int j = 0; j < 8; j++)
#pragma unroll
            for (int q = 0; q < 4; q++) acc[i][j][q] = 0.f;

    float a_st[16];
    uint4 a16_st[2];
    uint4 bh_st[2];

#define GLOAD(cc) do {                                                          \
    const int grow_ = bRow + lrow;                                              \
    if ((cc) < nc1) {                                                           \
        const int k0_ = (cc) << 5;                                              \
        if (AHALF) {                                                            \
            if (grow_ < M) {                                                    \
                const __half* ap_ = A1h + (size_t)grow_ * K1 + k0_ + lhalf * 16;\
                a16_st[0] = ((const uint4*)ap_)[0];                             \
                a16_st[1] = ((const uint4*)ap_)[1];                             \
            } else {                                                            \
                a16_st[0] = make_uint4(0,0,0,0); a16_st[1] = make_uint4(0,0,0,0);\
            }                                                                   \
        } else {                                                                \
            if (grow_ < M) {                                                    \
                const float* ap_ = A1f + (size_t)grow_ * K1 + k0_ + lhalf * 16; \
                *(float4*)(a_st + 0)  = ((const float4*)ap_)[0];                \
                *(float4*)(a_st + 4)  = ((const float4*)ap_)[1];                \
                *(float4*)(a_st + 8)  = ((const float4*)ap_)[2];                \
                *(float4*)(a_st + 12) = ((const float4*)ap_)[3];                \
            } else {                                                            \
                _Pragma("unroll") for (int j_ = 0; j_ < 16; j_++) a_st[j_] = 0.f;\
            }                                                                   \
        }                                                                       \
        const size_t bo_ = (size_t)(bCol + lrow) * K1 + ((cc) << 5) + lhalf * 16;\
        bh_st[0] = ((const uint4*)(B1h + bo_))[0];                              \
        bh_st[1] = ((const uint4*)(B1h + bo_))[1];                              \
    } else {                                                                    \
        const int k0_ = ((cc) - nc1) << 5;                                      \
        if (grow_ < M) {                                                        \
            const float* ap_ = A2 + (size_t)grow_ * K2 + k0_ + lhalf * 16;      \
            *(float4*)(a_st + 0)  = ((const float4*)ap_)[0];                    \
            *(float4*)(a_st + 4)  = ((const float4*)ap_)[1];                    \
            *(float4*)(a_st + 8)  = ((const float4*)ap_)[2];                    \
            *(float4*)(a_st + 12) = ((const float4*)ap_)[3];                    \
        } else {                                                                \
            _Pragma("unroll") for (int j_ = 0; j_ < 16; j_++) a_st[j_] = 0.f;   \
        }                                                                       \
        const size_t bo_ = (size_t)(bCol + lrow) * K2 + k0_ + lhalf * 16;       \
        bh_st[0] = ((const uint4*)(B2h + bo_))[0];                              \
        bh_st[1] = ((const uint4*)(B2h + bo_))[1];                              \
    }                                                                           \
} while (0)

#define SSTORE(buf) do {                                                        \
    char* base_ = smb + (buf) * BUFB;                                          \
    const uint32_t ro_ = lrow * RSTR + lhalf * 32;                              \
    if (AHALF) {                                                                \
        *(uint4*)(base_ + ro_)      = a16_st[0];                                \
        *(uint4*)(base_ + ro_ + 16) = a16_st[1];                                \
    } else {                                                                    \
        uint32_t hi_[8], lo_[8];                                                \
        _Pragma("unroll") for (int j_ = 0; j_ < 8; j_++) {                      \
            float f0_ = a_st[2*j_], f1_ = a_st[2*j_+1];                         \
            __half h0_ = __float2half_rn(f0_), h1_ = __float2half_rn(f1_);      \
            float v0_ = __half2float(h0_), v1_ = __half2float(h1_);             \
            hi_[j_] = packh2(v0_, v1_);                                         \
            lo_[j_] = packh2(f0_ - v0_, f1_ - v1_);                             \
        }                                                                       \
        *(uint4*)(base_ + ro_)      = make_uint4(hi_[0],hi_[1],hi_[2],hi_[3]);  \
        *(uint4*)(base_ + ro_ + 16) = make_uint4(hi_[4],hi_[5],hi_[6],hi_[7]);  \
        if (!SINGLE) {                                                          \
            *(uint4*)(base_ + MATB + ro_)      = make_uint4(lo_[0],lo_[1],lo_[2],lo_[3]);\
            *(uint4*)(base_ + MATB + ro_ + 16) = make_uint4(lo_[4],lo_[5],lo_[6],lo_[7]);\
        }                                                                       \
    }                                                                           \
    *(uint4*)(base_ + 2*MATB + ro_)      = bh_st[0];                            \
    *(uint4*)(base_ + 2*MATB + ro_ + 16) = bh_st[1];                            \
} while (0)

#define COMPUTE(buf) do {                                                       \
    const uint32_t ah_ = sb + (buf) * BUFB;                                     \
    const uint32_t al_ = ah_ + MATB, bhp_ = ah_ + 2*MATB;                       \
    _Pragma("unroll") for (int ks_ = 0; ks_ < 2; ks_++) {                       \
        uint32_t aH_[2][4], aL_[2][4], bH_[4][4];                               \
        const int arow_ = wm * 32 + (lane & 15);                                \
        const int acol_ = ks_ * 32 + ((lane >> 4) << 4);                        \
        ldsm4(aH_[0], ah_ + arow_ * RSTR + acol_);                              \
        ldsm4(aH_[1], ah_ + (arow_ + 16) * RSTR + acol_);                       \
        if (!SINGLE && !AHALF) {                                                \
            ldsm4(aL_[0], al_ + arow_ * RSTR + acol_);                          \
            ldsm4(aL_[1], al_ + (arow_ + 16) * RSTR + acol_);                   \
        }                                                                       \
        const int br_ = lane & 7, bg_ = lane >> 3;                              \
        const int brow_ = wn * 64 + ((bg_ >> 1) << 3) + br_;                    \
        const int bcol_ = ks_ * 32 + ((bg_ & 1) << 4);                          \
        _Pragma("unroll") for (int nj_ = 0; nj_ < 4; nj_++) {                   \
            ldsm4(bH_[nj_], bhp_ + (brow_ + nj_ * 16) * RSTR + bcol_);          \
        }                                                                       \
        _Pragma("unroll") for (int mi_ = 0; mi_ < 2; mi_++)                     \
        _Pragma("unroll") for (int ni_ = 0; ni_ < 8; ni_++) {                   \
            const uint32_t* bh2_ = &bH_[ni_ >> 1][(ni_ & 1) * 2];               \
            mma16816(acc[mi_][ni_], aH_[mi_], bh2_);                            \
            if (!SINGLE && !AHALF) mma16816(acc[mi_][ni_], aL_[mi_], bh2_);     \
        }                                                                       \
    }                                                                           \
} while (0)

    GLOAD(0);
    SSTORE(0);
    __syncthreads();
    for (int c = 0; c < nc; c++) {
        if (c + 1 < nc) GLOAD(c + 1);
        COMPUTE(c & 1);
        if (c + 1 < nc) SSTORE((c + 1) & 1);
        __syncthreads();
    }

#pragma unroll
    for (int mi = 0; mi < 2; mi++) {
        const int r0 = bRow + wm * 32 + mi * 16 + (lane >> 2);
#pragma unroll
        for (int ni = 0; ni < 8; ni++) {
            const int col = bCol + wn * 64 + ni * 8 + (lane & 3) * 2;
            const float b0 = bias[col], b1 = bias[col + 1];
            if (r0 < M) {
                float c0 = acc[mi][ni][0] + b0, c1 = acc[mi][ni][1] + b1;
                if (RELU) { c0 = fmaxf(c0, 0.f); c1 = fmaxf(c1, 0.f); }
                if (C)  *(float2*)(C + (size_t)r0 * N + col) = make_float2(c0, c1);
                if (Ch) *(uint32_t*)(Ch + (size_t)r0 * N + col) = packh2(c0, c1);
            }
            if (r0 + 8 < M) {
                float c2 = acc[mi][ni][2] + b0, c3 = acc[mi][ni][3] + b1;
                if (RELU) { c2 = fmaxf(c2, 0.f); c3 = fmaxf(c3, 0.f); }
                if (C)  *(float2*)(C + (size_t)(r0 + 8) * N + col) = make_float2(c2, c3);
                if (Ch) *(uint32_t*)(Ch + (size_t)(r0 + 8) * N + col) = packh2(c2, c3);
            }
        }
    }
#undef GLOAD
#undef SSTORE
#undef COMPUTE
}

// ---------------- weight prep: W[K][N] fp32 -> T [N][K] fp16 ----------------
__global__ void k_wprep(const float* __restrict__ W, __half* __restrict__ Th,
                        int K, int N) {
    __shared__ float s[32][33];
    int n0 = blockIdx.x * 32, k0 = blockIdx.y * 32;
    for (int r = threadIdx.y; r < 32; r += 8)
        s[r][threadIdx.x] = W[(size_t)(k0 + r) * N + n0 + threadIdx.x];
    __syncthreads();
    for (int r = threadIdx.y; r < 32; r += 8) {
        float f = s[threadIdx.x][r];
        Th[(size_t)(n0 + r) * K + k0 + threadIdx.x] = __float2half_rn(f);
    }
}

// ---------------- CSR build ----------------
__global__ void k_zeroi(int* __restrict__ p, unsigned n) {
    unsigned i = blockIdx.x * blockDim.x + threadIdx.x;
    if (i < n) p[i] = 0;
}
__global__ void k_count(const int* __restrict__ dst, int* __restrict__ cnt) {
    unsigned e = blockIdx.x * blockDim.x + threadIdx.x;
    if (e >= TT * EE) return;
    int t = e / EE;
    atomicAdd(&cnt[t * NN + dst[e]], 1);
}
__global__ void k_scan(const int* __restrict__ cnt, int* __restrict__ rowptr,
                       int* __restrict__ cursor) {
    int t = blockIdx.x;
    __shared__ int sdata[1024];
    __shared__ int carry_s;
    if (threadIdx.x == 0) carry_s = t * EE;
    __syncthreads();
    for (int c0 = 0; c0 < NN; c0 += 1024) {
        int i = c0 + threadIdx.x;
        int v = (i < NN) ? cnt[t * NN + i] : 0;
        sdata[threadIdx.x] = v;
        __syncthreads();
        for (int off = 1; off < 1024; off <<= 1) {
            int add = (threadIdx.x >= (unsigned)off) ? sdata[threadIdx.x - off] : 0;
            __syncthreads();
            sdata[threadIdx.x] += add;
            __syncthreads();
        }
        int excl = sdata[threadIdx.x] - v;
        if (i < NN) {
            int r = carry_s + excl;
            rowptr[t * NN + i] = r;
            cursor[t * NN + i] = r;
        }
        __syncthreads();
        if (threadIdx.x == 0) carry_s += sdata[1023];
        __syncthreads();
    }
}
__global__ void k_fill(const int* __restrict__ src, const int* __restrict__ dst,
                       int* __restrict__ cursor, int* __restrict__ eidx) {
    unsigned e = blockIdx.x * blockDim.x + threadIdx.x;
    if (e >= TT * EE) return;
    int t = e / EE;
    int pos = atomicAdd(&cursor[t * NN + dst[e]], 1);
    eidx[pos] = t * NN + src[e];
}
// CSR mean-aggregate: warp per node row; F = F4PL*128 floats
template<int F4PL>
__global__ void k_agg(const float* __restrict__ x, const int* __restrict__ rowptr,
                      const int* __restrict__ cnt, const int* __restrict__ eidx,
                      float* __restrict__ agg) {
    int w = threadIdx.x >> 5, lane = threadIdx.x & 31;
    unsigned n = blockIdx.x * 8 + w;
    if (n >= MB) return;
    const int F = F4PL * 128;
    int beg = rowptr[n], c = cnt[n];
    float4 acc[F4PL];
#pragma unroll
    for (int j = 0; j < F4PL; j++) acc[j] = make_float4(0.f, 0.f, 0.f, 0.f);
    int i = 0;
    for (; i + 1 < c; i += 2) {
        int s0 = eidx[beg + i], s1 = eidx[beg + i + 1];
        const float4* r0 = (const float4*)(x + (size_t)s0 * F);
        const float4* r1 = (const float4*)(x + (size_t)s1 * F);
#pragma unroll
        for (int j = 0; j < F4PL; j++) {
            float4 a = r0[lane + 32 * j], b = r1[lane + 32 * j];
            acc[j].x += a.x + b.x; acc[j].y += a.y + b.y;
            acc[j].z += a.z + b.z; acc[j].w += a.w + b.w;
        }
    }
    if (i < c) {
        const float4* r0 = (const float4*)(x + (size_t)eidx[beg + i] * F);
#pragma unroll
        for (int j = 0; j < F4PL; j++) {
            float4 a = r0[lane + 32 * j];
            acc[j].x += a.x; acc[j].y += a.y; acc[j].z += a.z; acc[j].w += a.w;
        }
    }
    float sc = 1.0f / (float)(c > 0 ? c : 1);
    float4* dst = (float4*)(agg + (size_t)n * F);
#pragma unroll
    for (int j = 0; j < F4PL; j++) {
        acc[j].x *= sc; acc[j].y *= sc; acc[j].z *= sc; acc[j].w *= sc;
        dst[lane + 32 * j] = acc[j];
    }
}

// ---------------- misc kernels ----------------
__global__ void k_normgather(const float* __restrict__ h2, const int* __restrict__ idx,
                             float* __restrict__ att_out, float* __restrict__ hbuf, int off) {
    int w = threadIdx.x >> 5, lane = threadIdx.x & 31;
    unsigned tp = blockIdx.x * 8 + w;
    int t = tp >> 12, p = tp & 4095;
    int n = idx[t * PP + p];
    const float* row = h2 + ((size_t)t * NN + n) * HH;
    float v[8]; float ss = 0.f;
#pragma unroll
    for (int i = 0; i < 8; i++) { v[i] = row[lane + i * 32]; ss += v[i] * v[i]; }
#pragma unroll
    for (int o = 16; o; o >>= 1) ss += __shfl_xor_sync(0xffffffffu, ss, o);
    float inv = 1.0f / fmaxf(sqrtf(ss), 1e-12f);
    size_t o0 = (size_t)tp * DDm + off;
#pragma unroll
    for (int i = 0; i < 8; i++) {
        float val = v[i] * inv;
        att_out[o0 + lane + i * 32] = val;
        hbuf[o0 + lane + i * 32] = val;
    }
}
// attention: block per (p,head); writes fp16 o (consumed by single-product Wo GEMM)
__global__ void k_attn(const float* __restrict__ qkv, __half* __restrict__ oh) {
    int p = blockIdx.x, h = blockIdx.y;
    int tid = threadIdx.x;
    __shared__ float qs[TT][64], ks[TT][64], vs[TT][64];
    __shared__ float att[TT][4];
    size_t base = (size_t)p * 1536 + h * 64 + tid;
#pragma unroll
    for (int t = 0; t < TT; t++) {
        size_t off = (size_t)t * PP * 1536 + base;
        qs[t][tid] = qkv[off];
        ks[t][tid] = qkv[off + 512];
        vs[t][tid] = qkv[off + 1024];
    }
    __syncthreads();
    {
        int t = tid >> 2, j = tid & 3, s = t - j;
        float sc = -INFINITY;
        if (s >= 0) {
            float a = 0.f;
#pragma unroll
            for (int d = 0; d < 64; d++) a += qs[t][d] * ks[s][d];
            sc = a * 0.125f;
        }
        att[t][j] = sc;
    }
    __syncthreads();
    if (tid < TT) {
        float m = -INFINITY;
#pragma unroll
        for (int j = 0; j < 4; j++) m = fmaxf(m, att[tid][j]);
        float sum = 0.f, e[4];
#pragma unroll
        for (int j = 0; j < 4; j++) {
            float x = att[tid][j];
            float ee = (x == -INFINITY) ? 0.f : expf(x - m);
            e[j] = ee; sum += ee;
        }
        float inv = 1.0f / sum;
#pragma unroll
        for (int j = 0; j < 4; j++) att[tid][j] = e[j] * inv;
    }
    __syncthreads();
    size_t obase = (size_t)p * DDm + h * 64 + tid;
#pragma unroll
    for (int t = 0; t < TT; t++) {
        float a = 0.f;
#pragma unroll
        for (int j = 0; j < 4; j++) {
            int s = t - j;
            if (s >= 0) a += att[t][j] * vs[s][tid];
        }
        oh[(size_t)t * PP * DDm + obase] = __float2half_rn(a);
    }
}
__global__ void k_ln(const float* __restrict__ r, const float* __restrict__ g,
                     const float* __restrict__ b) {
    int w = threadIdx.x >> 5, lane = threadIdx.x & 31;
    size_t row = (size_t)blockIdx.x * 8 + w;
    float* xr = g_h + row * DDm;
    const float* rr = r + row * DDm;
    float v[16]; float s = 0.f;
#pragma unroll
    for (int i = 0; i < 16; i++) {
        int c = lane + i * 32;
        float t = xr[c] + rr[c];
        v[i] = t; s += t;
    }
#pragma unroll
    for (int o = 16; o; o >>= 1) s += __shfl_xor_sync(0xffffffffu, s, o);
    float mean = s * (1.0f / DDm);
    float vs = 0.f;
#pragma unroll
    for (int i = 0; i < 16; i++) { float d = v[i] - mean; vs += d * d; }
#pragma unroll
    for (int o = 16; o; o >>= 1) vs += __shfl_xor_sync(0xffffffffu, vs, o);
    float inv = rsqrtf(vs * (1.0f / DDm) + 1e-5f);
#pragma unroll
    for (int i = 0; i < 16; i++) {
        int c = lane + i * 32;
        xr[c] = (v[i] - mean) * inv * g[c] + b[c];
    }
}
__global__ void k_out(const float* __restrict__ wout, float* __restrict__ out) {
    int w = threadIdx.x >> 5, lane = threadIdx.x & 31;
    size_t row = (size_t)blockIdx.x * 8 + w;
    const float* hr = g_h + row * DDm;
    float s = 0.f;
#pragma unroll
    for (int i = 0; i < 16; i++) { int c = lane + i * 32; s += hr[c] * wout[c]; }
#pragma unroll
    for (int o = 16; o; o >>= 1) s += __shfl_xor_sync(0xffffffffu, s, o);
    if (lane == 0) out[row] = s;
}

// =======================================================================================
extern "C" void kernel_launch(void* const* d_in, const int* in_sizes, int n_in,
                              void* d_out, int out_size) {
    const float* x_i  = (const float*)d_in[0];
    const float* x_j  = (const float*)d_in[1];
    const int* src_i  = (const int*)d_in[2];
    const int* dst_i  = (const int*)d_in[3];
    const int* src_j  = (const int*)d_in[4];
    const int* dst_j  = (const int*)d_in[5];
    const int* idx_i  = (const int*)d_in[6];
    const int* idx_j  = (const int*)d_in[7];
    const float* W1s  = (const float*)d_in[8];
    const float* W1n  = (const float*)d_in[9];
    const float* b1   = (const float*)d_in[10];
    const float* W2s  = (const float*)d_in[11];
    const float* W2n  = (const float*)d_in[12];
    const float* b2   = (const float*)d_in[13];
    const float* Wq   = (const float*)d_in[14];
    const float* Wk   = (const float*)d_in[15];
    const float* Wv   = (const float*)d_in[16];
    const float* bq   = (const float*)d_in[17];
    const float* bk   = (const float*)d_in[18];
    const float* bv   = (const float*)d_in[19];
    const float* Wo   = (const float*)d_in[20];
    const float* bo   = (const float*)d_in[21];
    const float* Wf1  = (const float*)d_in[22];
    const float* bf1  = (const float*)d_in[23];
    const float* Wf2  = (const float*)d_in[24];
    const float* bf2  = (const float*)d_in[25];
    const float* g1   = (const float*)d_in[26];
    const float* bg1  = (const float*)d_in[27];
    const float* g2   = (const float*)d_in[28];
    const float* bg2  = (const float*)d_in[29];
    const float* Wout = (const float*)d_in[30];
    float* out = (float*)d_out;

    float *p_aggB, *p_h1B, *p_h2B, *p_h, *p_qkv, *p_proj, *p_bqkv;
    __half *p_oh, *p_ffh;
    int *p_cnt, *p_rowptr, *p_cursor, *p_eidx;
    __half* p_w;
    cudaGetSymbolAddress((void**)&p_cnt,    g_cnt);
    cudaGetSymbolAddress((void**)&p_rowptr, g_rowptr);
    cudaGetSymbolAddress((void**)&p_cursor, g_cursor);
    cudaGetSymbolAddress((void**)&p_eidx,   g_eidx);
    cudaGetSymbolAddress((void**)&p_aggB,   g_aggB);
    cudaGetSymbolAddress((void**)&p_h1B,    g_h1B);
    cudaGetSymbolAddress((void**)&p_h2B,    g_h2B);
    cudaGetSymbolAddress((void**)&p_h,      g_h);
    cudaGetSymbolAddress((void**)&p_qkv,    g_qkv);
    cudaGetSymbolAddress((void**)&p_oh,     g_oh);
    cudaGetSymbolAddress((void**)&p_ffh,    g_ffh);
    cudaGetSymbolAddress((void**)&p_proj,   g_proj);
    cudaGetSymbolAddress((void**)&p_bqkv,   g_bqkv);
    cudaGetSymbolAddress((void**)&p_w,      g_w);

    cudaFuncSetAttribute(gemm_mma<false,false,false>, cudaFuncAttributeMaxDynamicSharedMemorySize, GSMEM);
    cudaFuncSetAttribute(gemm_mma<true, true, false>, cudaFuncAttributeMaxDynamicSharedMemorySize, GSMEM);
    cudaFuncSetAttribute(gemm_mma<false,true, false>, cudaFuncAttributeMaxDynamicSharedMemorySize, GSMEM);
    cudaFuncSetAttribute(gemm_mma<false,true, true >, cudaFuncAttributeMaxDynamicSharedMemorySize, GSMEM);

    // ---- stream fork (capture-safe: event fork off the capturing default stream) ----
    cudaStream_t s1;
    cudaStreamCreate(&s1);
    cudaEvent_t evF, evW, evJ;
    cudaEventCreateWithFlags(&evF, cudaEventDisableTiming);
    cudaEventCreateWithFlags(&evW, cudaEventDisableTiming);
    cudaEventCreateWithFlags(&evJ, cudaEventDisableTiming);
    cudaEventRecord(evF, 0);
    cudaStreamWaitEvent(s1, evF, 0);

    // ---- weight prep on default stream ----
    size_t off = 0;
    auto prep = [&](const float* W, int K, int N) -> size_t {
        size_t b = off;
        k_wprep<<<dim3(N/32, K/32), dim3(32, 8)>>>(W, p_w + b, K, N);
        off += (size_t)K * N;
        return b;
    };
    size_t oW1s = prep(W1s, DIN, HH), oW1n = prep(W1n, DIN, HH);
    size_t oW2s = prep(W2s, HH, HH),  oW2n = prep(W2n, HH, HH);
    cudaEventRecord(evW, 0);   // SAGE weights ready

    size_t oQKV[2];
    for (int l = 0; l < 2; l++) {
        size_t b = off; off += (size_t)1536 * DDm;
        const size_t KN = (size_t)DDm * DDm;
        k_wprep<<<dim3(DDm/32, DDm/32), dim3(32, 8)>>>(Wq + (size_t)l*KN, p_w + b,        DDm, DDm);
        k_wprep<<<dim3(DDm/32, DDm/32), dim3(32, 8)>>>(Wk + (size_t)l*KN, p_w + b + KN,   DDm, DDm);
        k_wprep<<<dim3(DDm/32, DDm/32), dim3(32, 8)>>>(Wv + (size_t)l*KN, p_w + b + 2*KN, DDm, DDm);
        oQKV[l] = b;
    }
    size_t oWo[2], oWf1[2], oWf2[2];
    for (int l = 0; l < 2; l++) {
        oWo[l]  = prep(Wo  + (size_t)l*DDm*DDm, DDm, DDm);
        oWf1[l] = prep(Wf1 + (size_t)l*DDm*FFD, DDm, FFD);
        oWf2[l] = prep(Wf2 + (size_t)l*FFD*DDm, FFD, DDm);
    }
    auto BH = [&](size_t b) { return p_w + b; };

    for (int l = 0; l < 2; l++) {
        cudaMemcpyAsync(p_bqkv + l*1536,        bq + l*DDm, DDm*4, cudaMemcpyDeviceToDevice);
        cudaMemcpyAsync(p_bqkv + l*1536 + 512,  bk + l*DDm, DDm*4, cudaMemcpyDeviceToDevice);
        cudaMemcpyAsync(p_bqkv + l*1536 + 1024, bv + l*DDm, DDm*4, cudaMemcpyDeviceToDevice);
    }

    // ---------- GraphSAGE: two independent graph pipelines on two streams ----------
    for (int gsel = 0; gsel < 2; gsel++) {
        cudaStream_t st = gsel ? s1 : (cudaStream_t)0;
        const float* x  = gsel ? x_j   : x_i;
        const int* src  = gsel ? src_j : src_i;
        const int* dstp = gsel ? dst_j : dst_i;
        const int* idx  = gsel ? idx_j : idx_i;
        int*   cnt    = p_cnt    + (size_t)gsel * MB;
        int*   rowptr = p_rowptr + (size_t)gsel * MB;
        int*   cursor = p_cursor + (size_t)gsel * MB;
        int*   eidx   = p_eidx   + (size_t)gsel * TT * EE;
        float* aggB   = p_aggB   + (size_t)gsel * MB * HH;
        float* h1B    = p_h1B    + (size_t)gsel * MB * HH;
        float* h2B    = p_h2B    + (size_t)gsel * MB * HH;

        k_zeroi<<<(MB + 255)/256, 256, 0, st>>>(cnt, MB);
        k_count<<<(TT*EE + 255)/256, 256, 0, st>>>(dstp, cnt);
        k_scan <<<TT, 1024, 0, st>>>(cnt, rowptr, cursor);
        k_fill <<<(TT*EE + 255)/256, 256, 0, st>>>(src, dstp, cursor, eidx);
        k_agg<1><<<(MB + 7)/8, 256, 0, st>>>(x, rowptr, cnt, eidx, aggB);

        if (gsel == 1) cudaStreamWaitEvent(st, evW, 0);

        gemm_mma<true,true,false><<<dim3(HH/128, (MB + 127)/128), 256, GSMEM, st>>>(
            x, BH(oW1s), DIN, aggB, BH(oW1n), DIN, b1, h1B, nullptr, MB, HH);

        k_agg<2><<<(MB + 7)/8, 256, 0, st>>>(h1B, rowptr, cnt, eidx, aggB);
        gemm_mma<false,true,false><<<dim3(HH/128, (MB + 127)/128), 256, GSMEM, st>>>(
            h1B, BH(oW2s), HH, aggB, BH(oW2n), HH, b2, h2B, nullptr, MB, HH);

        k_normgather<<<TPR/8, 256, 0, st>>>(h2B, idx, out, p_h, gsel * HH);
    }
    cudaEventRecord(evJ, s1);
    cudaStreamWaitEvent(0, evJ, 0);

    // ---------- transformer (L=2) ----------
    for (int l = 0; l < 2; l++) {
        // QKV: keep 2-product (softmax-sensitive)
        gemm_mma<false,false,false><<<dim3(1536/128, TPR/128), 256, GSMEM>>>(
            p_h, BH(oQKV[l]), DDm, nullptr, nullptr, 0,
            p_bqkv + l*1536, p_qkv, nullptr, TPR, 1536);

        k_attn<<<dim3(PP, 8), 64>>>(p_qkv, p_oh);

        // Wo: single-product, fp16 A direct from attention
        gemm_mma<false,true,true><<<dim3(DDm/128, TPR/128), 256, GSMEM>>>(
            p_oh, BH(oWo[l]), DDm, nullptr, nullptr, 0,
            bo + l*DDm, p_proj, nullptr, TPR, DDm);
        k_ln<<<TPR/8, 256>>>(p_proj, g1 + l*DDm, bg1 + l*DDm);

        // FF1: single-product, emits fp16 only (consumed by FF2's fp16-A path)
        gemm_mma<true,true,false><<<dim3(FFD/128, TPR/128), 256, GSMEM>>>(
            p_h, BH(oWf1[l]), DDm, nullptr, nullptr, 0,
            bf1 + l*FFD, nullptr, p_ffh, TPR, FFD);
        // FF2: single-product, fp16 A direct
        gemm_mma<false,true,true><<<dim3(DDm/128, TPR/128), 256, GSMEM>>>(
            p_ffh, BH(oWf2[l]), FFD, nullptr, nullptr, 0,
            bf2 + l*DDm, p_proj, nullptr, TPR, DDm);
        k_ln<<<TPR/8, 256>>>(p_proj, g2 + l*DDm, bg2 + l*DDm);
    }

    k_out<<<TPR/8, 256>>>(Wout, out + (size_t)TPR * DDm);
}

// round 12
// speedup vs baseline: 1.5894x; 1.1142x over previous
#include <cuda_runtime.h>
#include <cuda_fp16.h>
#include <math.h>
#include <stdint.h>

#define NN   20000
#define EE   320000
#define TT   16
#define PP   4096
#define DIN  128
#define HH   256
#define DDm  512
#define FFD  2048
#define TPR  (TT*PP)   // 65536
#define MB   (TT*NN)   // 320000 batched rows

// ---------------- scratch (static device globals; no allocation) ----------------
__device__ int   g_cnt   [2*MB];
__device__ int   g_rowptr[2*MB];
__device__ int   g_cursor[2*MB];
__device__ int   g_eidx  [2*TT*EE];
__device__ float g_aggB[(size_t)2*MB*HH];
__device__ __half g_h1h[(size_t)2*MB*HH];
__device__ float g_h2B [(size_t)2*MB*HH];
__device__ float g_h   [(size_t)TPR*DDm];
__device__ __half g_qkvh[(size_t)TPR*1536];
__device__ __half g_oh [(size_t)TPR*DDm];
__device__ __half g_ffh[(size_t)TPR*FFD];
__device__ float g_proj[(size_t)TPR*DDm];
__device__ float g_bqkv[2*1536];
__device__ __half g_w[6488064];

// ---------------- helpers ----------------
__device__ __forceinline__ uint32_t smem_u32(const void* p) {
    uint32_t a;
    asm("{ .reg .u64 t; cvta.to.shared.u64 t, %1; cvt.u32.u64 %0, t; }" : "=r"(a) : "l"(p));
    return a;
}
__device__ __forceinline__ void ldsm4(uint32_t* r, uint32_t addr) {
    asm volatile("ldmatrix.sync.aligned.m8n8.x4.shared.b16 {%0,%1,%2,%3}, [%4];"
                 : "=r"(r[0]), "=r"(r[1]), "=r"(r[2]), "=r"(r[3]) : "r"(addr));
}
__device__ __forceinline__ void mma16816(float* c, const uint32_t* a, const uint32_t* b) {
    asm volatile("mma.sync.aligned.m16n8k16.row.col.f32.f16.f16.f32 "
                 "{%0,%1,%2,%3}, {%4,%5,%6,%7}, {%8,%9}, {%0,%1,%2,%3};"
                 : "+f"(c[0]), "+f"(c[1]), "+f"(c[2]), "+f"(c[3])
                 : "r"(a[0]), "r"(a[1]), "r"(a[2]), "r"(a[3]), "r"(b[0]), "r"(b[1]));
}
__device__ __forceinline__ uint32_t packh2(float a, float b) {
    __half2 t = __floats2half2_rn(a, b);
    return *reinterpret_cast<uint32_t*>(&t);
}

// smem geometry: rows of 32 fp16 padded to 80 bytes (conflict-free ldmatrix)
#define RSTR  80
#define MATB  (128*RSTR)
#define BUFB  (3*MATB)     // Ah, Al, Bh
#define GSMEM (2*BUFB)     // double buffered = 61440

// ---------------- HMMA GEMM: C = A1@W1 (+ A2@W2) + bias, opt ReLU ------
// SINGLE=false: A split to fp16 hi+lo, two products (err ~2^-11, B rounding only).
// SINGLE=true : one product, A rounded to fp16.
// AHALF=true  : A1 is already fp16 (implies SINGLE); A2 (if any) is fp32, rounded.
// C (fp32) and Ch (fp16) outputs each optional.
template<bool RELU, bool SINGLE, bool AHALF>
__global__ void __launch_bounds__(256)
gemm_mma(const void* __restrict__ A1v, const __half* __restrict__ B1h, int K1,
         const float* __restrict__ A2, const __half* __restrict__ B2h, int K2,
         const float* __restrict__ bias, float* __restrict__ C,
         __half* __restrict__ Ch, int M, int N) {
    extern __shared__ char smb[];
    const uint32_t sb = smem_u32(smb);
    const int tid = threadIdx.x, lane = tid & 31, wid = tid >> 5;
    const int bRow = blockIdx.y * 128, bCol = blockIdx.x * 128;
    const int wm = wid & 3, wn = wid >> 2;
    const int lrow = tid >> 1, lhalf = tid & 1;

    const float*  A1f = (const float*)A1v;
    const __half* A1h = (const __half*)A1v;

    const int nc1 = K1 >> 5;
    const int nc  = nc1 + (K2 >> 5);

    float acc[2][8][4];
#pragma unroll
    for (int i = 0; i < 2; i++)
#pragma unroll
        for (int j = 0; j < 8; j++)
#pragma unroll
            for (int q = 0; q < 4; q++) acc[i][j][q] = 0.f;

    float a_st[16];
    uint4 a16_st[2];
    uint4 bh_st[2];

#define GLOAD(cc) do {                                                          \
    const int grow_ = bRow + lrow;                                              \
    if ((cc) < nc1) {                                                           \
        const int k0_ = (cc) << 5;                                              \
        if (AHALF) {                                                            \
            if (grow_ < M) {                                                    \
                const __half* ap_ = A1h + (size_t)grow_ * K1 + k0_ + lhalf * 16;\
                a16_st[0] = ((const uint4*)ap_)[0];                             \
                a16_st[1] = ((const uint4*)ap_)[1];                             \
            } else {                                                            \
                a16_st[0] = make_uint4(0,0,0,0); a16_st[1] = make_uint4(0,0,0,0);\
            }                                                                   \
        } else {                                                                \
            if (grow_ < M) {                                                    \
                const float* ap_ = A1f + (size_t)grow_ * K1 + k0_ + lhalf * 16; \
                *(float4*)(a_st + 0)  = ((const float4*)ap_)[0];                \
                *(float4*)(a_st + 4)  = ((const float4*)ap_)[1];                \
                *(float4*)(a_st + 8)  = ((const float4*)ap_)[2];                \
                *(float4*)(a_st + 12) = ((const float4*)ap_)[3];                \
            } else {                                                            \
                _Pragma("unroll") for (int j_ = 0; j_ < 16; j_++) a_st[j_] = 0.f;\
            }                                                                   \
        }                                                                       \
        const size_t bo_ = (size_t)(bCol + lrow) * K1 + k0_ + lhalf * 16;       \
        bh_st[0] = ((const uint4*)(B1h + bo_))[0];                              \
        bh_st[1] = ((const uint4*)(B1h + bo_))[1];                              \
    } else {                                                                    \
        const int k0_ = ((cc) - nc1) << 5;                                      \
        if (grow_ < M) {                                                        \
            const float* ap_ = A2 + (size_t)grow_ * K2 + k0_ + lhalf * 16;      \
            *(float4*)(a_st + 0)  = ((const float4*)ap_)[0];                    \
            *(float4*)(a_st + 4)  = ((const float4*)ap_)[1];                    \
            *(float4*)(a_st + 8)  = ((const float4*)ap_)[2];                    \
            *(float4*)(a_st + 12) = ((const float4*)ap_)[3];                    \
        } else {                                                                \
            _Pragma("unroll") for (int j_ = 0; j_ < 16; j_++) a_st[j_] = 0.f;   \
        }                                                                       \
        const size_t bo_ = (size_t)(bCol + lrow) * K2 + k0_ + lhalf * 16;       \
        bh_st[0] = ((const uint4*)(B2h + bo_))[0];                              \
        bh_st[1] = ((const uint4*)(B2h + bo_))[1];                              \
    }                                                                           \
} while (0)

#define SSTORE(buf, is2) do {                                                   \
    char* base_ = smb + (buf) * BUFB;                                          \
    const uint32_t ro_ = lrow * RSTR + lhalf * 32;                              \
    if (AHALF && !(is2)) {                                                      \
        *(uint4*)(base_ + ro_)      = a16_st[0];                                \
        *(uint4*)(base_ + ro_ + 16) = a16_st[1];                                \
    } else {                                                                    \
        uint32_t hi_[8], lo_[8];                                                \
        _Pragma("unroll") for (int j_ = 0; j_ < 8; j_++) {                      \
            float f0_ = a_st[2*j_], f1_ = a_st[2*j_+1];                         \
            __half h0_ = __float2half_rn(f0_), h1_ = __float2half_rn(f1_);      \
            float v0_ = __half2float(h0_), v1_ = __half2float(h1_);             \
            hi_[j_] = packh2(v0_, v1_);                                         \
            lo_[j_] = packh2(f0_ - v0_, f1_ - v1_);                             \
        }                                                                       \
        *(uint4*)(base_ + ro_)      = make_uint4(hi_[0],hi_[1],hi_[2],hi_[3]);  \
        *(uint4*)(base_ + ro_ + 16) = make_uint4(hi_[4],hi_[5],hi_[6],hi_[7]);  \
        if (!SINGLE) {                                                          \
            *(uint4*)(base_ + MATB + ro_)      = make_uint4(lo_[0],lo_[1],lo_[2],lo_[3]);\
            *(uint4*)(base_ + MATB + ro_ + 16) = make_uint4(lo_[4],lo_[5],lo_[6],lo_[7]);\
        }                                                                       \
    }                                                                           \
    *(uint4*)(base_ + 2*MATB + ro_)      = bh_st[0];                            \
    *(uint4*)(base_ + 2*MATB + ro_ + 16) = bh_st[1];                            \
} while (0)

#define COMPUTE(buf) do {                                                       \
    const uint32_t ah_ = sb + (buf) * BUFB;                                     \
    const uint32_t al_ = ah_ + MATB, bhp_ = ah_ + 2*MATB;                       \
    _Pragma("unroll") for (int ks_ = 0; ks_ < 2; ks_++) {                       \
        uint32_t aH_[2][4], aL_[2][4], bH_[4][4];                               \
        const int arow_ = wm * 32 + (lane & 15);                                \
        const int acol_ = ks_ * 32 + ((lane >> 4) << 4);                        \
        ldsm4(aH_[0], ah_ + arow_ * RSTR + acol_);                              \
        ldsm4(aH_[1], ah_ + (arow_ + 16) * RSTR + acol_);                       \
        if (!SINGLE && !AHALF) {                                                \
            ldsm4(aL_[0], al_ + arow_ * RSTR + acol_);                          \
            ldsm4(aL_[1], al_ + (arow_ + 16) * RSTR + acol_);                   \
        }                                                                       \
        const int br_ = lane & 7, bg_ = lane >> 3;                              \
        const int brow_ = wn * 64 + ((bg_ >> 1) << 3) + br_;                    \
        const int bcol_ = ks_ * 32 + ((bg_ & 1) << 4);                          \
        _Pragma("unroll") for (int nj_ = 0; nj_ < 4; nj_++) {                   \
            ldsm4(bH_[nj_], bhp_ + (brow_ + nj_ * 16) * RSTR + bcol_);          \
        }                                                                       \
        _Pragma("unroll") for (int mi_ = 0; mi_ < 2; mi_++)                     \
        _Pragma("unroll") for (int ni_ = 0; ni_ < 8; ni_++) {                   \
            const uint32_t* bh2_ = &bH_[ni_ >> 1][(ni_ & 1) * 2];               \
            mma16816(acc[mi_][ni_], aH_[mi_], bh2_);                            \
            if (!SINGLE && !AHALF) mma16816(acc[mi_][ni_], aL_[mi_], bh2_);     \
        }                                                                       \
    }                                                                           \
} while (0)

    GLOAD(0);
    SSTORE(0, 0 >= nc1);
    __syncthreads();
    for (int c = 0; c < nc; c++) {
        if (c + 1 < nc) GLOAD(c + 1);
        COMPUTE(c & 1);
        if (c + 1 < nc) SSTORE((c + 1) & 1, (c + 1) >= nc1);
        __syncthreads();
    }

#pragma unroll
    for (int mi = 0; mi < 2; mi++) {
        const int r0 = bRow + wm * 32 + mi * 16 + (lane >> 2);
#pragma unroll
        for (int ni = 0; ni < 8; ni++) {
            const int col = bCol + wn * 64 + ni * 8 + (lane & 3) * 2;
            const float b0 = bias[col], b1 = bias[col + 1];
            if (r0 < M) {
                float c0 = acc[mi][ni][0] + b0, c1 = acc[mi][ni][1] + b1;
                if (RELU) { c0 = fmaxf(c0, 0.f); c1 = fmaxf(c1, 0.f); }
                if (C)  *(float2*)(C + (size_t)r0 * N + col) = make_float2(c0, c1);
                if (Ch) *(uint32_t*)(Ch + (size_t)r0 * N + col) = packh2(c0, c1);
            }
            if (r0 + 8 < M) {
                float c2 = acc[mi][ni][2] + b0, c3 = acc[mi][ni][3] + b1;
                if (RELU) { c2 = fmaxf(c2, 0.f); c3 = fmaxf(c3, 0.f); }
                if (C)  *(float2*)(C + (size_t)(r0 + 8) * N + col) = make_float2(c2, c3);
                if (Ch) *(uint32_t*)(Ch + (size_t)(r0 + 8) * N + col) = packh2(c2, c3);
            }
        }
    }
#undef GLOAD
#undef SSTORE
#undef COMPUTE
}

// ---------------- weight prep: W[K][N] fp32 -> T [N][K] fp16 ----------------
__global__ void k_wprep(const float* __restrict__ W, __half* __restrict__ Th,
                        int K, int N) {
    __shared__ float s[32][33];
    int n0 = blockIdx.x * 32, k0 = blockIdx.y * 32;
    for (int r = threadIdx.y; r < 32; r += 8)
        s[r][threadIdx.x] = W[(size_t)(k0 + r) * N + n0 + threadIdx.x];
    __syncthreads();
    for (int r = threadIdx.y; r < 32; r += 8) {
        float f = s[threadIdx.x][r];
        Th[(size_t)(n0 + r) * K + k0 + threadIdx.x] = __float2half_rn(f);
    }
}

// ---------------- CSR build ----------------
__global__ void k_zeroi(int* __restrict__ p, unsigned n) {
    unsigned i = blockIdx.x * blockDim.x + threadIdx.x;
    if (i < n) p[i] = 0;
}
__global__ void k_count(const int* __restrict__ dst, int* __restrict__ cnt) {
    unsigned e = blockIdx.x * blockDim.x + threadIdx.x;
    if (e >= TT * EE) return;
    int t = e / EE;
    atomicAdd(&cnt[t * NN + dst[e]], 1);
}
__global__ void k_scan(const int* __restrict__ cnt, int* __restrict__ rowptr,
                       int* __restrict__ cursor) {
    int t = blockIdx.x;
    __shared__ int sdata[1024];
    __shared__ int carry_s;
    if (threadIdx.x == 0) carry_s = t * EE;
    __syncthreads();
    for (int c0 = 0; c0 < NN; c0 += 1024) {
        int i = c0 + threadIdx.x;
        int v = (i < NN) ? cnt[t * NN + i] : 0;
        sdata[threadIdx.x] = v;
        __syncthreads();
        for (int off = 1; off < 1024; off <<= 1) {
            int add = (threadIdx.x >= (unsigned)off) ? sdata[threadIdx.x - off] : 0;
            __syncthreads();
            sdata[threadIdx.x] += add;
            __syncthreads();
        }
        int excl = sdata[threadIdx.x] - v;
        if (i < NN) {
            int r = carry_s + excl;
            rowptr[t * NN + i] = r;
            cursor[t * NN + i] = r;
        }
        __syncthreads();
        if (threadIdx.x == 0) carry_s += sdata[1023];
        __syncthreads();
    }
}
__global__ void k_fill(const int* __restrict__ src, const int* __restrict__ dst,
                       int* __restrict__ cursor, int* __restrict__ eidx) {
    unsigned e = blockIdx.x * blockDim.x + threadIdx.x;
    if (e >= TT * EE) return;
    int t = e / EE;
    int pos = atomicAdd(&cursor[t * NN + dst[e]], 1);
    eidx[pos] = t * NN + src[e];
}
// CSR mean-aggregate fp32 in/out: warp per node; F = F4PL*128 floats
template<int F4PL>
__global__ void k_agg(const float* __restrict__ x, const int* __restrict__ rowptr,
                      const int* __restrict__ cnt, const int* __restrict__ eidx,
                      float* __restrict__ agg) {
    int w = threadIdx.x >> 5, lane = threadIdx.x & 31;
    unsigned n = blockIdx.x * 8 + w;
    if (n >= MB) return;
    const int F = F4PL * 128;
    int beg = rowptr[n], c = cnt[n];
    float4 acc[F4PL];
#pragma unroll
    for (int j = 0; j < F4PL; j++) acc[j] = make_float4(0.f, 0.f, 0.f, 0.f);
    int i = 0;
    for (; i + 1 < c; i += 2) {
        int s0 = eidx[beg + i], s1 = eidx[beg + i + 1];
        const float4* r0 = (const float4*)(x + (size_t)s0 * F);
        const float4* r1 = (const float4*)(x + (size_t)s1 * F);
#pragma unroll
        for (int j = 0; j < F4PL; j++) {
            float4 a = r0[lane + 32 * j], b = r1[lane + 32 * j];
            acc[j].x += a.x + b.x; acc[j].y += a.y + b.y;
            acc[j].z += a.z + b.z; acc[j].w += a.w + b.w;
        }
    }
    if (i < c) {
        const float4* r0 = (const float4*)(x + (size_t)eidx[beg + i] * F);
#pragma unroll
        for (int j = 0; j < F4PL; j++) {
            float4 a = r0[lane + 32 * j];
            acc[j].x += a.x; acc[j].y += a.y; acc[j].z += a.z; acc[j].w += a.w;
        }
    }
    float sc = 1.0f / (float)(c > 0 ? c : 1);
    float4* dst = (float4*)(agg + (size_t)n * F);
#pragma unroll
    for (int j = 0; j < F4PL; j++) {
        acc[j].x *= sc; acc[j].y *= sc; acc[j].z *= sc; acc[j].w *= sc;
        dst[lane + 32 * j] = acc[j];
    }
}
// CSR mean-aggregate fp16 in, fp32 accum+out: F=256 halfs; lane loads one uint4 (8 halfs)
__global__ void k_aggh256(const __half* __restrict__ x, const int* __restrict__ rowptr,
                          const int* __restrict__ cnt, const int* __restrict__ eidx,
                          float* __restrict__ agg) {
    int w = threadIdx.x >> 5, lane = threadIdx.x & 31;
    unsigned n = blockIdx.x * 8 + w;
    if (n >= MB) return;
    int beg = rowptr[n], c = cnt[n];
    float acc[8];
#pragma unroll
    for (int j = 0; j < 8; j++) acc[j] = 0.f;
    int i = 0;
    for (; i + 1 < c; i += 2) {
        int s0 = eidx[beg + i], s1 = eidx[beg + i + 1];
        uint4 v0 = *(const uint4*)(x + (size_t)s0 * 256 + lane * 8);
        uint4 v1 = *(const uint4*)(x + (size_t)s1 * 256 + lane * 8);
        const __half2* h0 = (const __half2*)&v0;
        const __half2* h1 = (const __half2*)&v1;
#pragma unroll
        for (int j = 0; j < 4; j++) {
            float2 a = __half22float2(h0[j]), b = __half22float2(h1[j]);
            acc[2*j]   += a.x + b.x;
            acc[2*j+1] += a.y + b.y;
        }
    }
    if (i < c) {
        uint4 v0 = *(const uint4*)(x + (size_t)eidx[beg + i] * 256 + lane * 8);
        const __half2* h0 = (const __half2*)&v0;
#pragma unroll
        for (int j = 0; j < 4; j++) {
            float2 a = __half22float2(h0[j]);
            acc[2*j]   += a.x;
            acc[2*j+1] += a.y;
        }
    }
    float sc = 1.0f / (float)(c > 0 ? c : 1);
    float* dst = agg + (size_t)n * 256 + lane * 8;
    float4 o0 = make_float4(acc[0]*sc, acc[1]*sc, acc[2]*sc, acc[3]*sc);
    float4 o1 = make_float4(acc[4]*sc, acc[5]*sc, acc[6]*sc, acc[7]*sc);
    ((float4*)dst)[0] = o0;
    ((float4*)dst)[1] = o1;
}

// ---------------- misc kernels ----------------
__global__ void k_normgather(const float* __restrict__ h2, const int* __restrict__ idx,
                             float* __restrict__ att_out, float* __restrict__ hbuf, int off) {
    int w = threadIdx.x >> 5, lane = threadIdx.x & 31;
    unsigned tp = blockIdx.x * 8 + w;
    int t = tp >> 12, p = tp & 4095;
    int n = idx[t * PP + p];
    const float* row = h2 + ((size_t)t * NN + n) * HH;
    float v[8]; float ss = 0.f;
#pragma unroll
    for (int i = 0; i < 8; i++) { v[i] = row[lane + i * 32]; ss += v[i] * v[i]; }
#pragma unroll
    for (int o = 16; o; o >>= 1) ss += __shfl_xor_sync(0xffffffffu, ss, o);
    float inv = 1.0f / fmaxf(sqrtf(ss), 1e-12f);
    size_t o0 = (size_t)tp * DDm + off;
#pragma unroll
    for (int i = 0; i < 8; i++) {
        float val = v[i] * inv;
        att_out[o0 + lane + i * 32] = val;
        hbuf[o0 + lane + i * 32] = val;
    }
}
// attention: block per (p,head); fp16 qkv in, fp16 o out
__global__ void k_attn(const __half* __restrict__ qkv, __half* __restrict__ oh) {
    int p = blockIdx.x, h = blockIdx.y;
    int tid = threadIdx.x;
    __shared__ float qs[TT][64], ks[TT][64], vs[TT][64];
    __shared__ float att[TT][4];
    size_t base = (size_t)p * 1536 + h * 64 + tid;
#pragma unroll
    for (int t = 0; t < TT; t++) {
        size_t off = (size_t)t * PP * 1536 + base;
        qs[t][tid] = __half2float(qkv[off]);
        ks[t][tid] = __half2float(qkv[off + 512]);
        vs[t][tid] = __half2float(qkv[off + 1024]);
    }
    __syncthreads();
    {
        int t = tid >> 2, j = tid & 3, s = t - j;
        float sc = -INFINITY;
        if (s >= 0) {
            float a = 0.f;
#pragma unroll
            for (int d = 0; d < 64; d++) a += qs[t][d] * ks[s][d];
            sc = a * 0.125f;
        }
        att[t][j] = sc;
    }
    __syncthreads();
    if (tid < TT) {
        float m = -INFINITY;
#pragma unroll
        for (int j = 0; j < 4; j++) m = fmaxf(m, att[tid][j]);
        float sum = 0.f, e[4];
#pragma unroll
        for (int j = 0; j < 4; j++) {
            float x = att[tid][j];
            float ee = (x == -INFINITY) ? 0.f : expf(x - m);
            e[j] = ee; sum += ee;
        }
        float inv = 1.0f / sum;
#pragma unroll
        for (int j = 0; j < 4; j++) att[tid][j] = e[j] * inv;
    }
    __syncthreads();
    size_t obase = (size_t)p * DDm + h * 64 + tid;
#pragma unroll
    for (int t = 0; t < TT; t++) {
        float a = 0.f;
#pragma unroll
        for (int j = 0; j < 4; j++) {
            int s = t - j;
            if (s >= 0) a += att[t][j] * vs[s][tid];
        }
        oh[(size_t)t * PP * DDm + obase] = __float2half_rn(a);
    }
}
__global__ void k_ln(const float* __restrict__ r, const float* __restrict__ g,
                     const float* __restrict__ b) {
    int w = threadIdx.x >> 5, lane = threadIdx.x & 31;
    size_t row = (size_t)blockIdx.x * 8 + w;
    float* xr = g_h + row * DDm;
    const float* rr = r + row * DDm;
    float v[16]; float s = 0.f;
#pragma unroll
    for (int i = 0; i < 16; i++) {
        int c = lane + i * 32;
        float t = xr[c] + rr[c];
        v[i] = t; s += t;
    }
#pragma unroll
    for (int o = 16; o; o >>= 1) s += __shfl_xor_sync(0xffffffffu, s, o);
    float mean = s * (1.0f / DDm);
    float vs = 0.f;
#pragma unroll
    for (int i = 0; i < 16; i++) { float d = v[i] - mean; vs += d * d; }
#pragma unroll
    for (int o = 16; o; o >>= 1) vs += __shfl_xor_sync(0xffffffffu, vs, o);
    float inv = rsqrtf(vs * (1.0f / DDm) + 1e-5f);
#pragma unroll
    for (int i = 0; i < 16; i++) {
        int c = lane + i * 32;
        xr[c] = (v[i] - mean) * inv * g[c] + b[c];
    }
}
__global__ void k_out(const float* __restrict__ wout, float* __restrict__ out) {
    int w = threadIdx.x >> 5, lane = threadIdx.x & 31;
    size_t row = (size_t)blockIdx.x * 8 + w;
    const float* hr = g_h + row * DDm;
    float s = 0.f;
#pragma unroll
    for (int i = 0; i < 16; i++) { int c = lane + i * 32; s += hr[c] * wout[c]; }
#pragma unroll
    for (int o = 16; o; o >>= 1) s += __shfl_xor_sync(0xffffffffu, s, o);
    if (lane == 0) out[row] = s;
}

// =======================================================================================
extern "C" void kernel_launch(void* const* d_in, const int* in_sizes, int n_in,
                              void* d_out, int out_size) {
    const float* x_i  = (const float*)d_in[0];
    const float* x_j  = (const float*)d_in[1];
    const int* src_i  = (const int*)d_in[2];
    const int* dst_i  = (const int*)d_in[3];
    const int* src_j  = (const int*)d_in[4];
    const int* dst_j  = (const int*)d_in[5];
    const int* idx_i  = (const int*)d_in[6];
    const int* idx_j  = (const int*)d_in[7];
    const float* W1s  = (const float*)d_in[8];
    const float* W1n  = (const float*)d_in[9];
    const float* b1   = (const float*)d_in[10];
    const float* W2s  = (const float*)d_in[11];
    const float* W2n  = (const float*)d_in[12];
    const float* b2   = (const float*)d_in[13];
    const float* Wq   = (const float*)d_in[14];
    const float* Wk   = (const float*)d_in[15];
    const float* Wv   = (const float*)d_in[16];
    const float* bq   = (const float*)d_in[17];
    const float* bk   = (const float*)d_in[18];
    const float* bv   = (const float*)d_in[19];
    const float* Wo   = (const float*)d_in[20];
    const float* bo   = (const float*)d_in[21];
    const float* Wf1  = (const float*)d_in[22];
    const float* bf1  = (const float*)d_in[23];
    const float* Wf2  = (const float*)d_in[24];
    const float* bf2  = (const float*)d_in[25];
    const float* g1   = (const float*)d_in[26];
    const float* bg1  = (const float*)d_in[27];
    const float* g2   = (const float*)d_in[28];
    const float* bg2  = (const float*)d_in[29];
    const float* Wout = (const float*)d_in[30];
    float* out = (float*)d_out;

    float *p_aggB, *p_h2B, *p_h, *p_proj, *p_bqkv;
    __half *p_h1h, *p_qkvh, *p_oh, *p_ffh;
    int *p_cnt, *p_rowptr, *p_cursor, *p_eidx;
    __half* p_w;
    cudaGetSymbolAddress((void**)&p_cnt,    g_cnt);
    cudaGetSymbolAddress((void**)&p_rowptr, g_rowptr);
    cudaGetSymbolAddress((void**)&p_cursor, g_cursor);
    cudaGetSymbolAddress((void**)&p_eidx,   g_eidx);
    cudaGetSymbolAddress((void**)&p_aggB,   g_aggB);
    cudaGetSymbolAddress((void**)&p_h1h,    g_h1h);
    cudaGetSymbolAddress((void**)&p_h2B,    g_h2B);
    cudaGetSymbolAddress((void**)&p_h,      g_h);
    cudaGetSymbolAddress((void**)&p_qkvh,   g_qkvh);
    cudaGetSymbolAddress((void**)&p_oh,     g_oh);
    cudaGetSymbolAddress((void**)&p_ffh,    g_ffh);
    cudaGetSymbolAddress((void**)&p_proj,   g_proj);
    cudaGetSymbolAddress((void**)&p_bqkv,   g_bqkv);
    cudaGetSymbolAddress((void**)&p_w,      g_w);

    cudaFuncSetAttribute(gemm_mma<true, true, false>, cudaFuncAttributeMaxDynamicSharedMemorySize, GSMEM);
    cudaFuncSetAttribute(gemm_mma<false,true, false>, cudaFuncAttributeMaxDynamicSharedMemorySize, GSMEM);
    cudaFuncSetAttribute(gemm_mma<false,true, true >, cudaFuncAttributeMaxDynamicSharedMemorySize, GSMEM);

    // ---- stream fork (capture-safe: event fork off the capturing default stream) ----
    cudaStream_t s1;
    cudaStreamCreate(&s1);
    cudaEvent_t evF, evW, evJ;
    cudaEventCreateWithFlags(&evF, cudaEventDisableTiming);
    cudaEventCreateWithFlags(&evW, cudaEventDisableTiming);
    cudaEventCreateWithFlags(&evJ, cudaEventDisableTiming);
    cudaEventRecord(evF, 0);
    cudaStreamWaitEvent(s1, evF, 0);

    // ---- weight prep on default stream ----
    size_t off = 0;
    auto prep = [&](const float* W, int K, int N) -> size_t {
        size_t b = off;
        k_wprep<<<dim3(N/32, K/32), dim3(32, 8)>>>(W, p_w + b, K, N);
        off += (size_t)K * N;
        return b;
    };
    size_t oW1s = prep(W1s, DIN, HH), oW1n = prep(W1n, DIN, HH);
    size_t oW2s = prep(W2s, HH, HH),  oW2n = prep(W2n, HH, HH);
    cudaEventRecord(evW, 0);   // SAGE weights ready

    size_t oQKV[2];
    for (int l = 0; l < 2; l++) {
        size_t b = off; off += (size_t)1536 * DDm;
        const size_t KN = (size_t)DDm * DDm;
        k_wprep<<<dim3(DDm/32, DDm/32), dim3(32, 8)>>>(Wq + (size_t)l*KN, p_w + b,        DDm, DDm);
        k_wprep<<<dim3(DDm/32, DDm/32), dim3(32, 8)>>>(Wk + (size_t)l*KN, p_w + b + KN,   DDm, DDm);
        k_wprep<<<dim3(DDm/32, DDm/32), dim3(32, 8)>>>(Wv + (size_t)l*KN, p_w + b + 2*KN, DDm, DDm);
        oQKV[l] = b;
    }
    size_t oWo[2], oWf1[2], oWf2[2];
    for (int l = 0; l < 2; l++) {
        oWo[l]  = prep(Wo  + (size_t)l*DDm*DDm, DDm, DDm);
        oWf1[l] = prep(Wf1 + (size_t)l*DDm*FFD, DDm, FFD);
        oWf2[l] = prep(Wf2 + (size_t)l*FFD*DDm, FFD, DDm);
    }
    auto BH = [&](size_t b) { return p_w + b; };

    for (int l = 0; l < 2; l++) {
        cudaMemcpyAsync(p_bqkv + l*1536,        bq + l*DDm, DDm*4, cudaMemcpyDeviceToDevice);
        cudaMemcpyAsync(p_bqkv + l*1536 + 512,  bk + l*DDm, DDm*4, cudaMemcpyDeviceToDevice);
        cudaMemcpyAsync(p_bqkv + l*1536 + 1024, bv + l*DDm, DDm*4, cudaMemcpyDeviceToDevice);
    }

    // ---------- GraphSAGE: two independent graph pipelines on two streams ----------
    for (int gsel = 0; gsel < 2; gsel++) {
        cudaStream_t st = gsel ? s1 : (cudaStream_t)0;
        const float* x  = gsel ? x_j   : x_i;
        const int* src  = gsel ? src_j : src_i;
        const int* dstp = gsel ? dst_j : dst_i;
        const int* idx  = gsel ? idx_j : idx_i;
        int*   cnt    = p_cnt    + (size_t)gsel * MB;
        int*   rowptr = p_rowptr + (size_t)gsel * MB;
        int*   cursor = p_cursor + (size_t)gsel * MB;
        int*   eidx   = p_eidx   + (size_t)gsel * TT * EE;
        float* aggB   = p_aggB   + (size_t)gsel * MB * HH;
        __half* h1h   = p_h1h    + (size_t)gsel * MB * HH;
        float* h2B    = p_h2B    + (size_t)gsel * MB * HH;

        k_zeroi<<<(MB + 255)/256, 256, 0, st>>>(cnt, MB);
        k_count<<<(TT*EE + 255)/256, 256, 0, st>>>(dstp, cnt);
        k_scan <<<TT, 1024, 0, st>>>(cnt, rowptr, cursor);
        k_fill <<<(TT*EE + 255)/256, 256, 0, st>>>(src, dstp, cursor, eidx);
        k_agg<1><<<(MB + 7)/8, 256, 0, st>>>(x, rowptr, cnt, eidx, aggB);

        if (gsel == 1) cudaStreamWaitEvent(st, evW, 0);

        // layer 1: fp32 A single-product, emits fp16 h1 only
        gemm_mma<true,true,false><<<dim3(HH/128, (MB + 127)/128), 256, GSMEM, st>>>(
            x, BH(oW1s), DIN, aggB, BH(oW1n), DIN, b1, nullptr, h1h, MB, HH);

        // layer 2: fp16 gather-mean, fp16 A direct + fp32 agg
        k_aggh256<<<(MB + 7)/8, 256, 0, st>>>(h1h, rowptr, cnt, eidx, aggB);
        gemm_mma<false,true,true><<<dim3(HH/128, (MB + 127)/128), 256, GSMEM, st>>>(
            h1h, BH(oW2s), HH, aggB, BH(oW2n), HH, b2, h2B, nullptr, MB, HH);

        k_normgather<<<TPR/8, 256, 0, st>>>(h2B, idx, out, p_h, gsel * HH);
    }
    cudaEventRecord(evJ, s1);
    cudaStreamWaitEvent(0, evJ, 0);

    // ---------- transformer (L=2) ----------
    for (int l = 0; l < 2; l++) {
        // QKV: single-product, fp16 output
        gemm_mma<false,true,false><<<dim3(1536/128, TPR/128), 256, GSMEM>>>(
            p_h, BH(oQKV[l]), DDm, nullptr, nullptr, 0,
            p_bqkv + l*1536, nullptr, p_qkvh, TPR, 1536);

        k_attn<<<dim3(PP, 8), 64>>>(p_qkvh, p_oh);

        // Wo: single-product, fp16 A direct from attention
        gemm_mma<false,true,true><<<dim3(DDm/128, TPR/128), 256, GSMEM>>>(
            p_oh, BH(oWo[l]), DDm, nullptr, nullptr, 0,
            bo + l*DDm, p_proj, nullptr, TPR, DDm);
        k_ln<<<TPR/8, 256>>>(p_proj, g1 + l*DDm, bg1 + l*DDm);

        // FF1: single-product, emits fp16 only
        gemm_mma<true,true,false><<<dim3(FFD/128, TPR/128), 256, GSMEM>>>(
            p_h, BH(oWf1[l]), DDm, nullptr, nullptr, 0,
            bf1 + l*FFD, nullptr, p_ffh, TPR, FFD);
        // FF2: single-product, fp16 A direct
        gemm_mma<false,true,true><<<dim3(DDm/128, TPR/128), 256, GSMEM>>>(
            p_ffh, BH(oWf2[l]), FFD, nullptr, nullptr, 0,
            bf2 + l*DDm, p_proj, nullptr, TPR, DDm);
        k_ln<<<TPR/8, 256>>>(p_proj, g2 + l*DDm, bg2 + l*DDm);
    }

    k_out<<<TPR/8, 256>>>(Wout, out + (size_t)TPR * DDm);
}

// round 13
// speedup vs baseline: 1.6146x; 1.0159x over previous
#include <cuda_runtime.h>
#include <cuda_fp16.h>
#include <math.h>
#include <stdint.h>

#define NN   20000
#define EE   320000
#define TT   16
#define PP   4096
#define DIN  128
#define HH   256
#define DDm  512
#define FFD  2048
#define TPR  (TT*PP)   // 65536
#define MB   (TT*NN)   // 320000 batched rows

// ---------------- scratch (static device globals; no allocation) ----------------
__device__ int   g_cnt   [2*MB];
__device__ int   g_rowptr[2*MB];
__device__ int   g_cursor[2*MB];
__device__ int   g_eidx  [2*TT*EE];
__device__ __half g_xh [(size_t)2*MB*DIN];
__device__ float g_aggB[(size_t)2*MB*HH];
__device__ __half g_h1h[(size_t)2*MB*HH];
__device__ float g_h2B [(size_t)2*MB*HH];
__device__ float g_h   [(size_t)TPR*DDm];
__device__ __half g_qkvh[(size_t)TPR*1536];
__device__ __half g_oh [(size_t)TPR*DDm];
__device__ __half g_ffh[(size_t)TPR*FFD];
__device__ float g_proj[(size_t)TPR*DDm];
__device__ float g_bqkv[2*1536];
__device__ __half g_w[6488064];

// ---------------- helpers ----------------
__device__ __forceinline__ uint32_t smem_u32(const void* p) {
    uint32_t a;
    asm("{ .reg .u64 t; cvta.to.shared.u64 t, %1; cvt.u32.u64 %0, t; }" : "=r"(a) : "l"(p));
    return a;
}
__device__ __forceinline__ void ldsm4(uint32_t* r, uint32_t addr) {
    asm volatile("ldmatrix.sync.aligned.m8n8.x4.shared.b16 {%0,%1,%2,%3}, [%4];"
                 : "=r"(r[0]), "=r"(r[1]), "=r"(r[2]), "=r"(r[3]) : "r"(addr));
}
__device__ __forceinline__ void mma16816(float* c, const uint32_t* a, const uint32_t* b) {
    asm volatile("mma.sync.aligned.m16n8k16.row.col.f32.f16.f16.f32 "
                 "{%0,%1,%2,%3}, {%4,%5,%6,%7}, {%8,%9}, {%0,%1,%2,%3};"
                 : "+f"(c[0]), "+f"(c[1]), "+f"(c[2]), "+f"(c[3])
                 : "r"(a[0]), "r"(a[1]), "r"(a[2]), "r"(a[3]), "r"(b[0]), "r"(b[1]));
}
__device__ __forceinline__ uint32_t packh2(float a, float b) {
    __half2 t = __floats2half2_rn(a, b);
    return *reinterpret_cast<uint32_t*>(&t);
}

// smem geometry: rows of 32 fp16 padded to 80 bytes (conflict-free ldmatrix)
#define RSTR  80
#define MATB  (128*RSTR)
#define BUFB  (2*MATB)     // Ah, Bh (all GEMMs single-product now)
#define GSMEM (2*BUFB)     // double buffered = 40960  -> 2 CTAs/SM

// ---------------- HMMA GEMM (single-product fp16): C = A1@W1 (+ A2@W2) + bias ----
// AHALF: A1 already fp16; A2 (if present) always fp32, rounded on store.
// C (fp32) and Ch (fp16) outputs each optional.
template<bool RELU, bool AHALF>
__global__ void __launch_bounds__(256, 2)
gemm_mma(const void* __restrict__ A1v, const __half* __restrict__ B1h, int K1,
         const float* __restrict__ A2, const __half* __restrict__ B2h, int K2,
         const float* __restrict__ bias, float* __restrict__ C,
         __half* __restrict__ Ch, int M, int N) {
    extern __shared__ char smb[];
    const uint32_t sb = smem_u32(smb);
    const int tid = threadIdx.x, lane = tid & 31, wid = tid >> 5;
    const int bRow = blockIdx.y * 128, bCol = blockIdx.x * 128;
    const int wm = wid & 3, wn = wid >> 2;
    const int lrow = tid >> 1, lhalf = tid & 1;

    const float*  A1f = (const float*)A1v;
    const __half* A1h = (const __half*)A1v;

    const int nc1 = K1 >> 5;
    const int nc  = nc1 + (K2 >> 5);

    float acc[2][8][4];
#pragma unroll
    for (int i = 0; i < 2; i++)
#pragma unroll
        for (int j = 0; j < 8; j++)
#pragma unroll
            for (int q = 0; q < 4; q++) acc[i][j][q] = 0.f;

    float a_st[16];
    uint4 a16_st[2];
    uint4 bh_st[2];

#define GLOAD(cc) do {                                                          \
    const int grow_ = bRow + lrow;                                              \
    if ((cc) < nc1) {                                                           \
        const int k0_ = (cc) << 5;                                              \
        if (AHALF) {                                                            \
            if (grow_ < M) {                                                    \
                const __half* ap_ = A1h + (size_t)grow_ * K1 + k0_ + lhalf * 16;\
                a16_st[0] = ((const uint4*)ap_)[0];                             \
                a16_st[1] = ((const uint4*)ap_)[1];                             \
            } else {                                                            \
                a16_st[0] = make_uint4(0,0,0,0); a16_st[1] = make_uint4(0,0,0,0);\
            }                                                                   \
        } else {                                                                \
            if (grow_ < M) {                                                    \
                const float* ap_ = A1f + (size_t)grow_ * K1 + k0_ + lhalf * 16; \
                *(float4*)(a_st + 0)  = ((const float4*)ap_)[0];                \
                *(float4*)(a_st + 4)  = ((const float4*)ap_)[1];                \
                *(float4*)(a_st + 8)  = ((const float4*)ap_)[2];                \
                *(float4*)(a_st + 12) = ((const float4*)ap_)[3];                \
            } else {                                                            \
                _Pragma("unroll") for (int j_ = 0; j_ < 16; j_++) a_st[j_] = 0.f;\
            }                                                                   \
        }                                                                       \
        const size_t bo_ = (size_t)(bCol + lrow) * K1 + k0_ + lhalf * 16;       \
        bh_st[0] = ((const uint4*)(B1h + bo_))[0];                              \
        bh_st[1] = ((const uint4*)(B1h + bo_))[1];                              \
    } else {                                                                    \
        const int k0_ = ((cc) - nc1) << 5;                                      \
        if (grow_ < M) {                                                        \
            const float* ap_ = A2 + (size_t)grow_ * K2 + k0_ + lhalf * 16;      \
            *(float4*)(a_st + 0)  = ((const float4*)ap_)[0];                    \
            *(float4*)(a_st + 4)  = ((const float4*)ap_)[1];                    \
            *(float4*)(a_st + 8)  = ((const float4*)ap_)[2];                    \
            *(float4*)(a_st + 12) = ((const float4*)ap_)[3];                    \
        } else {                                                                \
            _Pragma("unroll") for (int j_ = 0; j_ < 16; j_++) a_st[j_] = 0.f;   \
        }                                                                       \
        const size_t bo_ = (size_t)(bCol + lrow) * K2 + k0_ + lhalf * 16;       \
        bh_st[0] = ((const uint4*)(B2h + bo_))[0];                              \
        bh_st[1] = ((const uint4*)(B2h + bo_))[1];                              \
    }                                                                           \
} while (0)

#define SSTORE(buf, is2) do {                                                   \
    char* base_ = smb + (buf) * BUFB;                                          \
    const uint32_t ro_ = lrow * RSTR + lhalf * 32;                              \
    if (AHALF && !(is2)) {                                                      \
        *(uint4*)(base_ + ro_)      = a16_st[0];                                \
        *(uint4*)(base_ + ro_ + 16) = a16_st[1];                                \
    } else {                                                                    \
        uint32_t hi_[8];                                                        \
        _Pragma("unroll") for (int j_ = 0; j_ < 8; j_++)                        \
            hi_[j_] = packh2(a_st[2*j_], a_st[2*j_+1]);                         \
        *(uint4*)(base_ + ro_)      = make_uint4(hi_[0],hi_[1],hi_[2],hi_[3]);  \
        *(uint4*)(base_ + ro_ + 16) = make_uint4(hi_[4],hi_[5],hi_[6],hi_[7]);  \
    }                                                                           \
    *(uint4*)(base_ + MATB + ro_)      = bh_st[0];                              \
    *(uint4*)(base_ + MATB + ro_ + 16) = bh_st[1];                              \
} while (0)

#define COMPUTE(buf) do {                                                       \
    const uint32_t ah_ = sb + (buf) * BUFB;                                     \
    const uint32_t bhp_ = ah_ + MATB;                                           \
    _Pragma("unroll") for (int ks_ = 0; ks_ < 2; ks_++) {                       \
        uint32_t aH_[2][4], bH_[4][4];                                          \
        const int arow_ = wm * 32 + (lane & 15);                                \
        const int acol_ = ks_ * 32 + ((lane >> 4) << 4);                        \
        ldsm4(aH_[0], ah_ + arow_ * RSTR + acol_);                              \
        ldsm4(aH_[1], ah_ + (arow_ + 16) * RSTR + acol_);                       \
        const int br_ = lane & 7, bg_ = lane >> 3;                              \
        const int brow_ = wn * 64 + ((bg_ >> 1) << 3) + br_;                    \
        const int bcol_ = ks_ * 32 + ((bg_ & 1) << 4);                          \
        _Pragma("unroll") for (int nj_ = 0; nj_ < 4; nj_++) {                   \
            ldsm4(bH_[nj_], bhp_ + (brow_ + nj_ * 16) * RSTR + bcol_);          \
        }                                                                       \
        _Pragma("unroll") for (int mi_ = 0; mi_ < 2; mi_++)                     \
        _Pragma("unroll") for (int ni_ = 0; ni_ < 8; ni_++) {                   \
            const uint32_t* bh2_ = &bH_[ni_ >> 1][(ni_ & 1) * 2];               \
            mma16816(acc[mi_][ni_], aH_[mi_], bh2_);                            \
        }                                                                       \
    }                                                                           \
} while (0)

    GLOAD(0);
    SSTORE(0, 0 >= nc1);
    __syncthreads();
    for (int c = 0; c < nc; c++) {
        if (c + 1 < nc) GLOAD(c + 1);
        COMPUTE(c & 1);
        if (c + 1 < nc) SSTORE((c + 1) & 1, (c + 1) >= nc1);
        __syncthreads();
    }

#pragma unroll
    for (int mi = 0; mi < 2; mi++) {
        const int r0 = bRow + wm * 32 + mi * 16 + (lane >> 2);
#pragma unroll
        for (int ni = 0; ni < 8; ni++) {
            const int col = bCol + wn * 64 + ni * 8 + (lane & 3) * 2;
            const float b0 = bias[col], b1 = bias[col + 1];
            if (r0 < M) {
                float c0 = acc[mi][ni][0] + b0, c1 = acc[mi][ni][1] + b1;
                if (RELU) { c0 = fmaxf(c0, 0.f); c1 = fmaxf(c1, 0.f); }
                if (C)  *(float2*)(C + (size_t)r0 * N + col) = make_float2(c0, c1);
                if (Ch) *(uint32_t*)(Ch + (size_t)r0 * N + col) = packh2(c0, c1);
            }
            if (r0 + 8 < M) {
                float c2 = acc[mi][ni][2] + b0, c3 = acc[mi][ni][3] + b1;
                if (RELU) { c2 = fmaxf(c2, 0.f); c3 = fmaxf(c3, 0.f); }
                if (C)  *(float2*)(C + (size_t)(r0 + 8) * N + col) = make_float2(c2, c3);
                if (Ch) *(uint32_t*)(Ch + (size_t)(r0 + 8) * N + col) = packh2(c2, c3);
            }
        }
    }
#undef GLOAD
#undef SSTORE
#undef COMPUTE
}

// ---------------- weight prep: W[K][N] fp32 -> T [N][K] fp16 ----------------
__global__ void k_wprep(const float* __restrict__ W, __half* __restrict__ Th,
                        int K, int N) {
    __shared__ float s[32][33];
    int n0 = blockIdx.x * 32, k0 = blockIdx.y * 32;
    for (int r = threadIdx.y; r < 32; r += 8)
        s[r][threadIdx.x] = W[(size_t)(k0 + r) * N + n0 + threadIdx.x];
    __syncthreads();
    for (int r = threadIdx.y; r < 32; r += 8) {
        float f = s[threadIdx.x][r];
        Th[(size_t)(n0 + r) * K + k0 + threadIdx.x] = __float2half_rn(f);
    }
}

// ---------------- fp32 -> fp16 elementwise (8 per thread) ----------------
__global__ void k_tohalf(const float* __restrict__ x, __half* __restrict__ y, unsigned n8) {
    unsigned i = blockIdx.x * blockDim.x + threadIdx.x;
    if (i >= n8) return;
    const float4* xp = (const float4*)(x) + 2 * (size_t)i;
    float4 a = xp[0], b = xp[1];
    uint4 o;
    o.x = packh2(a.x, a.y); o.y = packh2(a.z, a.w);
    o.z = packh2(b.x, b.y); o.w = packh2(b.z, b.w);
    ((uint4*)y)[i] = o;
}

// ---------------- CSR build ----------------
__global__ void k_zeroi(int* __restrict__ p, unsigned n) {
    unsigned i = blockIdx.x * blockDim.x + threadIdx.x;
    if (i < n) p[i] = 0;
}
__global__ void k_count(const int* __restrict__ dst, int* __restrict__ cnt) {
    unsigned e = blockIdx.x * blockDim.x + threadIdx.x;
    if (e >= TT * EE) return;
    int t = e / EE;
    atomicAdd(&cnt[t * NN + dst[e]], 1);
}
__global__ void k_scan(const int* __restrict__ cnt, int* __restrict__ rowptr,
                       int* __restrict__ cursor) {
    int t = blockIdx.x;
    __shared__ int sdata[1024];
    __shared__ int carry_s;
    if (threadIdx.x == 0) carry_s = t * EE;
    __syncthreads();
    for (int c0 = 0; c0 < NN; c0 += 1024) {
        int i = c0 + threadIdx.x;
        int v = (i < NN) ? cnt[t * NN + i] : 0;
        sdata[threadIdx.x] = v;
        __syncthreads();
        for (int off = 1; off < 1024; off <<= 1) {
            int add = (threadIdx.x >= (unsigned)off) ? sdata[threadIdx.x - off] : 0;
            __syncthreads();
            sdata[threadIdx.x] += add;
            __syncthreads();
        }
        int excl = sdata[threadIdx.x] - v;
        if (i < NN) {
            int r = carry_s + excl;
            rowptr[t * NN + i] = r;
            cursor[t * NN + i] = r;
        }
        __syncthreads();
        if (threadIdx.x == 0) carry_s += sdata[1023];
        __syncthreads();
    }
}
__global__ void k_fill(const int* __restrict__ src, const int* __restrict__ dst,
                       int* __restrict__ cursor, int* __restrict__ eidx) {
    unsigned e = blockIdx.x * blockDim.x + threadIdx.x;
    if (e >= TT * EE) return;
    int t = e / EE;
    int pos = atomicAdd(&cursor[t * NN + dst[e]], 1);
    eidx[pos] = t * NN + src[e];
}
// CSR mean-aggregate fp16 in (F=128 halfs), fp32 accum+out; lane loads uint2 (4 halfs)
__global__ void k_aggh128(const __half* __restrict__ x, const int* __restrict__ rowptr,
                          const int* __restrict__ cnt, const int* __restrict__ eidx,
                          float* __restrict__ agg) {
    int w = threadIdx.x >> 5, lane = threadIdx.x & 31;
    unsigned n = blockIdx.x * 8 + w;
    if (n >= MB) return;
    int beg = rowptr[n], c = cnt[n];
    float acc[4];
#pragma unroll
    for (int j = 0; j < 4; j++) acc[j] = 0.f;
    int i = 0;
    for (; i + 1 < c; i += 2) {
        int s0 = eidx[beg + i], s1 = eidx[beg + i + 1];
        uint2 v0 = *(const uint2*)(x + (size_t)s0 * DIN + lane * 4);
        uint2 v1 = *(const uint2*)(x + (size_t)s1 * DIN + lane * 4);
        const __half2* h0 = (const __half2*)&v0;
        const __half2* h1 = (const __half2*)&v1;
#pragma unroll
        for (int j = 0; j < 2; j++) {
            float2 a = __half22float2(h0[j]), b = __half22float2(h1[j]);
            acc[2*j]   += a.x + b.x;
            acc[2*j+1] += a.y + b.y;
        }
    }
    if (i < c) {
        uint2 v0 = *(const uint2*)(x + (size_t)eidx[beg + i] * DIN + lane * 4);
        const __half2* h0 = (const __half2*)&v0;
#pragma unroll
        for (int j = 0; j < 2; j++) {
            float2 a = __half22float2(h0[j]);
            acc[2*j]   += a.x;
            acc[2*j+1] += a.y;
        }
    }
    float sc = 1.0f / (float)(c > 0 ? c : 1);
    ((float4*)(agg + (size_t)n * DIN + lane * 4))[0] =
        make_float4(acc[0]*sc, acc[1]*sc, acc[2]*sc, acc[3]*sc);
}
// CSR mean-aggregate fp16 in (F=256 halfs), fp32 accum+out; lane loads uint4 (8 halfs)
__global__ void k_aggh256(const __half* __restrict__ x, const int* __restrict__ rowptr,
                          const int* __restrict__ cnt, const int* __restrict__ eidx,
                          float* __restrict__ agg) {
    int w = threadIdx.x >> 5, lane = threadIdx.x & 31;
    unsigned n = blockIdx.x * 8 + w;
    if (n >= MB) return;
    int beg = rowptr[n], c = cnt[n];
    float acc[8];
#pragma unroll
    for (int j = 0; j < 8; j++) acc[j] = 0.f;
    int i = 0;
    for (; i + 1 < c; i += 2) {
        int s0 = eidx[beg + i], s1 = eidx[beg + i + 1];
        uint4 v0 = *(const uint4*)(x + (size_t)s0 * 256 + lane * 8);
        uint4 v1 = *(const uint4*)(x + (size_t)s1 * 256 + lane * 8);
        const __half2* h0 = (const __half2*)&v0;
        const __half2* h1 = (const __half2*)&v1;
#pragma unroll
        for (int j = 0; j < 4; j++) {
            float2 a = __half22float2(h0[j]), b = __half22float2(h1[j]);
            acc[2*j]   += a.x + b.x;
            acc[2*j+1] += a.y + b.y;
        }
    }
    if (i < c) {
        uint4 v0 = *(const uint4*)(x + (size_t)eidx[beg + i] * 256 + lane * 8);
        const __half2* h0 = (const __half2*)&v0;
#pragma unroll
        for (int j = 0; j < 4; j++) {
            float2 a = __half22float2(h0[j]);
            acc[2*j]   += a.x;
            acc[2*j+1] += a.y;
        }
    }
    float sc = 1.0f / (float)(c > 0 ? c : 1);
    float* dst = agg + (size_t)n * 256 + lane * 8;
    ((float4*)dst)[0] = make_float4(acc[0]*sc, acc[1]*sc, acc[2]*sc, acc[3]*sc);
    ((float4*)dst)[1] = make_float4(acc[4]*sc, acc[5]*sc, acc[6]*sc, acc[7]*sc);
}

// ---------------- misc kernels ----------------
__global__ void k_normgather(const float* __restrict__ h2, const int* __restrict__ idx,
                             float* __restrict__ att_out, float* __restrict__ hbuf, int off) {
    int w = threadIdx.x >> 5, lane = threadIdx.x & 31;
    unsigned tp = blockIdx.x * 8 + w;
    int t = tp >> 12, p = tp & 4095;
    int n = idx[t * PP + p];
    const float* row = h2 + ((size_t)t * NN + n) * HH;
    float v[8]; float ss = 0.f;
#pragma unroll
    for (int i = 0; i < 8; i++) { v[i] = row[lane + i * 32]; ss += v[i] * v[i]; }
#pragma unroll
    for (int o = 16; o; o >>= 1) ss += __shfl_xor_sync(0xffffffffu, ss, o);
    float inv = 1.0f / fmaxf(sqrtf(ss), 1e-12f);
    size_t o0 = (size_t)tp * DDm + off;
#pragma unroll
    for (int i = 0; i < 8; i++) {
        float val = v[i] * inv;
        att_out[o0 + lane + i * 32] = val;
        hbuf[o0 + lane + i * 32] = val;
    }
}
__global__ void k_attn(const __half* __restrict__ qkv, __half* __restrict__ oh) {
    int p = blockIdx.x, h = blockIdx.y;
    int tid = threadIdx.x;
    __shared__ float qs[TT][64], ks[TT][64], vs[TT][64];
    __shared__ float att[TT][4];
    size_t base = (size_t)p * 1536 + h * 64 + tid;
#pragma unroll
    for (int t = 0; t < TT; t++) {
        size_t off = (size_t)t * PP * 1536 + base;
        qs[t][tid] = __half2float(qkv[off]);
        ks[t][tid] = __half2float(qkv[off + 512]);
        vs[t][tid] = __half2float(qkv[off + 1024]);
    }
    __syncthreads();
    {
        int t = tid >> 2, j = tid & 3, s = t - j;
        float sc = -INFINITY;
        if (s >= 0) {
            float a = 0.f;
#pragma unroll
            for (int d = 0; d < 64; d++) a += qs[t][d] * ks[s][d];
            sc = a * 0.125f;
        }
        att[t][j] = sc;
    }
    __syncthreads();
    if (tid < TT) {
        float m = -INFINITY;
#pragma unroll
        for (int j = 0; j < 4; j++) m = fmaxf(m, att[tid][j]);
        float sum = 0.f, e[4];
#pragma unroll
        for (int j = 0; j < 4; j++) {
            float x = att[tid][j];
            float ee = (x == -INFINITY) ? 0.f : expf(x - m);
            e[j] = ee; sum += ee;
        }
        float inv = 1.0f / sum;
#pragma unroll
        for (int j = 0; j < 4; j++) att[tid][j] = e[j] * inv;
    }
    __syncthreads();
    size_t obase = (size_t)p * DDm + h * 64 + tid;
#pragma unroll
    for (int t = 0; t < TT; t++) {
        float a = 0.f;
#pragma unroll
        for (int j = 0; j < 4; j++) {
            int s = t - j;
            if (s >= 0) a += att[t][j] * vs[s][tid];
        }
        oh[(size_t)t * PP * DDm + obase] = __float2half_rn(a);
    }
}
__global__ void k_ln(const float* __restrict__ r, const float* __restrict__ g,
                     const float* __restrict__ b) {
    int w = threadIdx.x >> 5, lane = threadIdx.x & 31;
    size_t row = (size_t)blockIdx.x * 8 + w;
    float* xr = g_h + row * DDm;
    const float* rr = r + row * DDm;
    float v[16]; float s = 0.f;
#pragma unroll
    for (int i = 0; i < 16; i++) {
        int c = lane + i * 32;
        float t = xr[c] + rr[c];
        v[i] = t; s += t;
    }
#pragma unroll
    for (int o = 16; o; o >>= 1) s += __shfl_xor_sync(0xffffffffu, s, o);
    float mean = s * (1.0f / DDm);
    float vs = 0.f;
#pragma unroll
    for (int i = 0; i < 16; i++) { float d = v[i] - mean; vs += d * d; }
#pragma unroll
    for (int o = 16; o; o >>= 1) vs += __shfl_xor_sync(0xffffffffu, vs, o);
    float inv = rsqrtf(vs * (1.0f / DDm) + 1e-5f);
#pragma unroll
    for (int i = 0; i < 16; i++) {
        int c = lane + i * 32;
        xr[c] = (v[i] - mean) * inv * g[c] + b[c];
    }
}
__global__ void k_out(const float* __restrict__ wout, float* __restrict__ out) {
    int w = threadIdx.x >> 5, lane = threadIdx.x & 31;
    size_t row = (size_t)blockIdx.x * 8 + w;
    const float* hr = g_h + row * DDm;
    float s = 0.f;
#pragma unroll
    for (int i = 0; i < 16; i++) { int c = lane + i * 32; s += hr[c] * wout[c]; }
#pragma unroll
    for (int o = 16; o; o >>= 1) s += __shfl_xor_sync(0xffffffffu, s, o);
    if (lane == 0) out[row] = s;
}

// =======================================================================================
extern "C" void kernel_launch(void* const* d_in, const int* in_sizes, int n_in,
                              void* d_out, int out_size) {
    const float* x_i  = (const float*)d_in[0];
    const float* x_j  = (const float*)d_in[1];
    const int* src_i  = (const int*)d_in[2];
    const int* dst_i  = (const int*)d_in[3];
    const int* src_j  = (const int*)d_in[4];
    const int* dst_j  = (const int*)d_in[5];
    const int* idx_i  = (const int*)d_in[6];
    const int* idx_j  = (const int*)d_in[7];
    const float* W1s  = (const float*)d_in[8];
    const float* W1n  = (const float*)d_in[9];
    const float* b1   = (const float*)d_in[10];
    const float* W2s  = (const float*)d_in[11];
    const float* W2n  = (const float*)d_in[12];
    const float* b2   = (const float*)d_in[13];
    const float* Wq   = (const float*)d_in[14];
    const float* Wk   = (const float*)d_in[15];
    const float* Wv   = (const float*)d_in[16];
    const float* bq   = (const float*)d_in[17];
    const float* bk   = (const float*)d_in[18];
    const float* bv   = (const float*)d_in[19];
    const float* Wo   = (const float*)d_in[20];
    const float* bo   = (const float*)d_in[21];
    const float* Wf1  = (const float*)d_in[22];
    const float* bf1  = (const float*)d_in[23];
    const float* Wf2  = (const float*)d_in[24];
    const float* bf2  = (const float*)d_in[25];
    const float* g1   = (const float*)d_in[26];
    const float* bg1  = (const float*)d_in[27];
    const float* g2   = (const float*)d_in[28];
    const float* bg2  = (const float*)d_in[29];
    const float* Wout = (const float*)d_in[30];
    float* out = (float*)d_out;

    float *p_aggB, *p_h2B, *p_h, *p_proj, *p_bqkv;
    __half *p_xh, *p_h1h, *p_qkvh, *p_oh, *p_ffh;
    int *p_cnt, *p_rowptr, *p_cursor, *p_eidx;
    __half* p_w;
    cudaGetSymbolAddress((void**)&p_cnt,    g_cnt);
    cudaGetSymbolAddress((void**)&p_rowptr, g_rowptr);
    cudaGetSymbolAddress((void**)&p_cursor, g_cursor);
    cudaGetSymbolAddress((void**)&p_eidx,   g_eidx);
    cudaGetSymbolAddress((void**)&p_xh,     g_xh);
    cudaGetSymbolAddress((void**)&p_aggB,   g_aggB);
    cudaGetSymbolAddress((void**)&p_h1h,    g_h1h);
    cudaGetSymbolAddress((void**)&p_h2B,    g_h2B);
    cudaGetSymbolAddress((void**)&p_h,      g_h);
    cudaGetSymbolAddress((void**)&p_qkvh,   g_qkvh);
    cudaGetSymbolAddress((void**)&p_oh,     g_oh);
    cudaGetSymbolAddress((void**)&p_ffh,    g_ffh);
    cudaGetSymbolAddress((void**)&p_proj,   g_proj);
    cudaGetSymbolAddress((void**)&p_bqkv,   g_bqkv);
    cudaGetSymbolAddress((void**)&p_w,      g_w);

    cudaFuncSetAttribute(gemm_mma<true, false>, cudaFuncAttributeMaxDynamicSharedMemorySize, GSMEM);
    cudaFuncSetAttribute(gemm_mma<false,false>, cudaFuncAttributeMaxDynamicSharedMemorySize, GSMEM);
    cudaFuncSetAttribute(gemm_mma<true, true >, cudaFuncAttributeMaxDynamicSharedMemorySize, GSMEM);
    cudaFuncSetAttribute(gemm_mma<false,true >, cudaFuncAttributeMaxDynamicSharedMemorySize, GSMEM);

    // ---- stream fork (capture-safe: event fork off the capturing default stream) ----
    cudaStream_t s1;
    cudaStreamCreate(&s1);
    cudaEvent_t evF, evW, evJ;
    cudaEventCreateWithFlags(&evF, cudaEventDisableTiming);
    cudaEventCreateWithFlags(&evW, cudaEventDisableTiming);
    cudaEventCreateWithFlags(&evJ, cudaEventDisableTiming);
    cudaEventRecord(evF, 0);
    cudaStreamWaitEvent(s1, evF, 0);

    // ---- weight prep on default stream ----
    size_t off = 0;
    auto prep = [&](const float* W, int K, int N) -> size_t {
        size_t b = off;
        k_wprep<<<dim3(N/32, K/32), dim3(32, 8)>>>(W, p_w + b, K, N);
        off += (size_t)K * N;
        return b;
    };
    size_t oW1s = prep(W1s, DIN, HH), oW1n = prep(W1n, DIN, HH);
    size_t oW2s = prep(W2s, HH, HH),  oW2n = prep(W2n, HH, HH);
    cudaEventRecord(evW, 0);   // SAGE weights ready

    size_t oQKV[2];
    for (int l = 0; l < 2; l++) {
        size_t b = off; off += (size_t)1536 * DDm;
        const size_t KN = (size_t)DDm * DDm;
        k_wprep<<<dim3(DDm/32, DDm/32), dim3(32, 8)>>>(Wq + (size_t)l*KN, p_w + b,        DDm, DDm);
        k_wprep<<<dim3(DDm/32, DDm/32), dim3(32, 8)>>>(Wk + (size_t)l*KN, p_w + b + KN,   DDm, DDm);
        k_wprep<<<dim3(DDm/32, DDm/32), dim3(32, 8)>>>(Wv + (size_t)l*KN, p_w + b + 2*KN, DDm, DDm);
        oQKV[l] = b;
    }
    size_t oWo[2], oWf1[2], oWf2[2];
    for (int l = 0; l < 2; l++) {
        oWo[l]  = prep(Wo  + (size_t)l*DDm*DDm, DDm, DDm);
        oWf1[l] = prep(Wf1 + (size_t)l*DDm*FFD, DDm, FFD);
        oWf2[l] = prep(Wf2 + (size_t)l*FFD*DDm, FFD, DDm);
    }
    auto BH = [&](size_t b) { return p_w + b; };

    for (int l = 0; l < 2; l++) {
        cudaMemcpyAsync(p_bqkv + l*1536,        bq + l*DDm, DDm*4, cudaMemcpyDeviceToDevice);
        cudaMemcpyAsync(p_bqkv + l*1536 + 512,  bk + l*DDm, DDm*4, cudaMemcpyDeviceToDevice);
        cudaMemcpyAsync(p_bqkv + l*1536 + 1024, bv + l*DDm, DDm*4, cudaMemcpyDeviceToDevice);
    }

    // ---------- GraphSAGE: two independent graph pipelines on two streams ----------
    for (int gsel = 0; gsel < 2; gsel++) {
        cudaStream_t st = gsel ? s1 : (cudaStream_t)0;
        const float* x  = gsel ? x_j   : x_i;
        const int* src  = gsel ? src_j : src_i;
        const int* dstp = gsel ? dst_j : dst_i;
        const int* idx  = gsel ? idx_j : idx_i;
        int*   cnt    = p_cnt    + (size_t)gsel * MB;
        int*   rowptr = p_rowptr + (size_t)gsel * MB;
        int*   cursor = p_cursor + (size_t)gsel * MB;
        int*   eidx   = p_eidx   + (size_t)gsel * TT * EE;
        __half* xh    = p_xh     + (size_t)gsel * MB * DIN;
        float* aggB   = p_aggB   + (size_t)gsel * MB * HH;
        __half* h1h   = p_h1h    + (size_t)gsel * MB * HH;
        float* h2B    = p_h2B    + (size_t)gsel * MB * HH;

        k_zeroi <<<(MB + 255)/256, 256, 0, st>>>(cnt, MB);
        k_count <<<(TT*EE + 255)/256, 256, 0, st>>>(dstp, cnt);
        k_scan  <<<TT, 1024, 0, st>>>(cnt, rowptr, cursor);
        k_fill  <<<(TT*EE + 255)/256, 256, 0, st>>>(src, dstp, cursor, eidx);
        k_tohalf<<<((unsigned)(MB*DIN/8) + 255)/256, 256, 0, st>>>(x, xh, (unsigned)(MB*DIN/8));
        k_aggh128<<<(MB + 7)/8, 256, 0, st>>>(xh, rowptr, cnt, eidx, aggB);

        if (gsel == 1) cudaStreamWaitEvent(st, evW, 0);

        // layer 1: fp16 x direct + fp32 agg (rounded); emits fp16 h1 only
        gemm_mma<true,true><<<dim3(HH/128, (MB + 127)/128), 256, GSMEM, st>>>(
            xh, BH(oW1s), DIN, aggB, BH(oW1n), DIN, b1, nullptr, h1h, MB, HH);

        // layer 2: fp16 gather-mean, fp16 A direct + fp32 agg
        k_aggh256<<<(MB + 7)/8, 256, 0, st>>>(h1h, rowptr, cnt, eidx, aggB);
        gemm_mma<false,true><<<dim3(HH/128, (MB + 127)/128), 256, GSMEM, st>>>(
            h1h, BH(oW2s), HH, aggB, BH(oW2n), HH, b2, h2B, nullptr, MB, HH);

        k_normgather<<<TPR/8, 256, 0, st>>>(h2B, idx, out, p_h, gsel * HH);
    }
    cudaEventRecord(evJ, s1);
    cudaStreamWaitEvent(0, evJ, 0);

    // ---------- transformer (L=2) ----------
    for (int l = 0; l < 2; l++) {
        gemm_mma<false,false><<<dim3(1536/128, TPR/128), 256, GSMEM>>>(
            p_h, BH(oQKV[l]), DDm, nullptr, nullptr, 0,
            p_bqkv + l*1536, nullptr, p_qkvh, TPR, 1536);

        k_attn<<<dim3(PP, 8), 64>>>(p_qkvh, p_oh);

        gemm_mma<false,true><<<dim3(DDm/128, TPR/128), 256, GSMEM>>>(
            p_oh, BH(oWo[l]), DDm, nullptr, nullptr, 0,
            bo + l*DDm, p_proj, nullptr, TPR, DDm);
        k_ln<<<TPR/8, 256>>>(p_proj, g1 + l*DDm, bg1 + l*DDm);

        gemm_mma<true,false><<<dim3(FFD/128, TPR/128), 256, GSMEM>>>(
            p_h, BH(oWf1[l]), DDm, nullptr, nullptr, 0,
            bf1 + l*FFD, nullptr, p_ffh, TPR, FFD);
        gemm_mma<false,true><<<dim3(DDm/128, TPR/128), 256, GSMEM>>>(
            p_ffh, BH(oWf2[l]), FFD, nullptr, nullptr, 0,
            bf2 + l*DDm, p_proj, nullptr, TPR, DDm);
        k_ln<<<TPR/8, 256>>>(p_proj, g2 + l*DDm, bg2 + l*DDm);
    }

    k_out<<<TPR/8, 256>>>(Wout, out + (size_t)TPR * DDm);
}

// round 15
// speedup vs baseline: 1.6822x; 1.0419x over previous
#include <cuda_runtime.h>
#include <cuda_fp16.h>
#include <math.h>
#include <stdint.h>

#define NN   20000
#define EE   320000
#define TT   16
#define PP   4096
#define DIN  128
#define HH   256
#define DDm  512
#define FFD  2048
#define TPR  (TT*PP)   // 65536
#define MB   (TT*NN)   // 320000 batched rows

// ---------------- scratch (static device globals; no allocation) ----------------
__device__ int   g_cnt   [2*MB];
__device__ int   g_rowptr[2*MB];
__device__ int   g_cursor[2*MB];
__device__ int   g_eidx  [2*TT*EE];
__device__ __half g_xh [(size_t)2*MB*DIN];
__device__ float g_aggB[(size_t)2*MB*HH];
__device__ __half g_h1h[(size_t)2*MB*HH];
__device__ float g_h2B [(size_t)2*MB*HH];
__device__ float g_h   [(size_t)TPR*DDm];
__device__ __half g_h16[(size_t)TPR*DDm];
__device__ __half g_qkvh[(size_t)TPR*1536];
__device__ __half g_oh [(size_t)TPR*DDm];
__device__ __half g_ffh[(size_t)TPR*FFD];
__device__ float g_proj[(size_t)TPR*DDm];
__device__ float g_bqkv[2*1536];
__device__ __half g_w[6488064];

// ---------------- helpers ----------------
__device__ __forceinline__ uint32_t smem_u32(const void* p) {
    uint32_t a;
    asm("{ .reg .u64 t; cvta.to.shared.u64 t, %1; cvt.u32.u64 %0, t; }" : "=r"(a) : "l"(p));
    return a;
}
__device__ __forceinline__ void ldsm4(uint32_t* r, uint32_t addr) {
    asm volatile("ldmatrix.sync.aligned.m8n8.x4.shared.b16 {%0,%1,%2,%3}, [%4];"
                 : "=r"(r[0]), "=r"(r[1]), "=r"(r[2]), "=r"(r[3]) : "r"(addr));
}
__device__ __forceinline__ void mma16816(float* c, const uint32_t* a, const uint32_t* b) {
    asm volatile("mma.sync.aligned.m16n8k16.row.col.f32.f16.f16.f32 "
                 "{%0,%1,%2,%3}, {%4,%5,%6,%7}, {%8,%9}, {%0,%1,%2,%3};"
                 : "+f"(c[0]), "+f"(c[1]), "+f"(c[2]), "+f"(c[3])
                 : "r"(a[0]), "r"(a[1]), "r"(a[2]), "r"(a[3]), "r"(b[0]), "r"(b[1]));
}
__device__ __forceinline__ uint32_t packh2(float a, float b) {
    __half2 t = __floats2half2_rn(a, b);
    return *reinterpret_cast<uint32_t*>(&t);
}

// smem geometry: rows of 32 fp16 padded to 80 bytes (conflict-free ldmatrix)
#define RSTR  80
#define MATB  (128*RSTR)
#define BUFB  (2*MATB)     // Ah, Bh
#define GSMEM (4*BUFB)     // 4-buffer ring = 81920 -> still 2 CTAs/SM

// ---------------- HMMA GEMM (single-product fp16): C = A1@W1 (+ A2@W2) + bias ----
// A1 always fp16 [M][K1]. A2 (optional) fp32 [M][K2], rounded on smem store.
// One syncthreads per TWO K-chunks (4-buffer ring).
// C (fp32) and Ch (fp16) outputs each optional.
template<bool RELU>
__global__ void __launch_bounds__(256, 2)
gemm_mma(const __half* __restrict__ A1, const __half* __restrict__ B1h, int K1,
         const float* __restrict__ A2, const __half* __restrict__ B2h, int K2,
         const float* __restrict__ bias, float* __restrict__ C,
         __half* __restrict__ Ch, int M, int N) {
    extern __shared__ char smb[];
    const uint32_t sb = smem_u32(smb);
    const int tid = threadIdx.x, lane = tid & 31, wid = tid >> 5;
    const int bRow = blockIdx.y * 128, bCol = blockIdx.x * 128;
    const int wm = wid & 3, wn = wid >> 2;
    const int lrow = tid >> 1, lhalf = tid & 1;

    const int nc1 = K1 >> 5;
    const int nc  = nc1 + (K2 >> 5);   // even, >= 4 for all call sites

    float acc[2][8][4];
#pragma unroll
    for (int i = 0; i < 2; i++)
#pragma unroll
        for (int j = 0; j < 8; j++)
#pragma unroll
            for (int q = 0; q < 4; q++) acc[i][j][q] = 0.f;

    float a_st[16];
    uint4 a16_st[2];
    uint4 bh_st[2];

#define GLOAD(cc) do {                                                          \
    const int grow_ = bRow + lrow;                                              \
    if ((cc) < nc1) {                                                           \
        const int k0_ = (cc) << 5;                                              \
        if (grow_ < M) {                                                        \
            const __half* ap_ = A1 + (size_t)grow_ * K1 + k0_ + lhalf * 16;     \
            a16_st[0] = ((const uint4*)ap_)[0];                                 \
            a16_st[1] = ((const uint4*)ap_)[1];                                 \
        } else {                                                                \
            a16_st[0] = make_uint4(0,0,0,0); a16_st[1] = make_uint4(0,0,0,0);   \
        }                                                                       \
        const size_t bo_ = (size_t)(bCol + lrow) * K1 + k0_ + lhalf * 16;       \
        bh_st[0] = ((const uint4*)(B1h + bo_))[0];                              \
        bh_st[1] = ((const uint4*)(B1h + bo_))[1];                              \
    } else {                                                                    \
        const int k0_ = ((cc) - nc1) << 5;                                      \
        if (grow_ < M) {                                                        \
            const float* ap_ = A2 + (size_t)grow_ * K2 + k0_ + lhalf * 16;      \
            *(float4*)(a_st + 0)  = ((const float4*)ap_)[0];                    \
            *(float4*)(a_st + 4)  = ((const float4*)ap_)[1];                    \
            *(float4*)(a_st + 8)  = ((const float4*)ap_)[2];                    \
            *(float4*)(a_st + 12) = ((const float4*)ap_)[3];                    \
        } else {                                                                \
            _Pragma("unroll") for (int j_ = 0; j_ < 16; j_++) a_st[j_] = 0.f;   \
        }                                                                       \
        const size_t bo_ = (size_t)(bCol + lrow) * K2 + k0_ + lhalf * 16;       \
        bh_st[0] = ((const uint4*)(B2h + bo_))[0];                              \
        bh_st[1] = ((const uint4*)(B2h + bo_))[1];                              \
    }                                                                           \
} while (0)

#define SSTORE(cc) do {                                                         \
    char* base_ = smb + ((cc) & 3) * BUFB;                                     \
    const uint32_t ro_ = lrow * RSTR + lhalf * 32;                              \
    if ((cc) < nc1) {                                                           \
        *(uint4*)(base_ + ro_)      = a16_st[0];                                \
        *(uint4*)(base_ + ro_ + 16) = a16_st[1];                                \
    } else {                                                                    \
        uint32_t hi_[8];                                                        \
        _Pragma("unroll") for (int j_ = 0; j_ < 8; j_++)                        \
            hi_[j_] = packh2(a_st[2*j_], a_st[2*j_+1]);                         \
        *(uint4*)(base_ + ro_)      = make_uint4(hi_[0],hi_[1],hi_[2],hi_[3]);  \
        *(uint4*)(base_ + ro_ + 16) = make_uint4(hi_[4],hi_[5],hi_[6],hi_[7]);  \
    }                                                                           \
    *(uint4*)(base_ + MATB + ro_)      = bh_st[0];                              \
    *(uint4*)(base_ + MATB + ro_ + 16) = bh_st[1];                              \
} while (0)

#define COMPUTE(cc) do {                                                        \
    const uint32_t ah_ = sb + ((cc) & 3) * BUFB;                                \
    const uint32_t bhp_ = ah_ + MATB;                                           \
    _Pragma("unroll") for (int ks_ = 0; ks_ < 2; ks_++) {                       \
        uint32_t aH_[2][4], bH_[4][4];                                          \
        const int arow_ = wm * 32 + (lane & 15);                                \
        const int acol_ = ks_ * 32 + ((lane >> 4) << 4);                        \
        ldsm4(aH_[0], ah_ + arow_ * RSTR + acol_);                              \
        ldsm4(aH_[1], ah_ + (arow_ + 16) * RSTR + acol_);                       \
        const int br_ = lane & 7, bg_ = lane >> 3;                              \
        const int brow_ = wn * 64 + ((bg_ >> 1) << 3) + br_;                    \
        const int bcol_ = ks_ * 32 + ((bg_ & 1) << 4);                          \
        _Pragma("unroll") for (int nj_ = 0; nj_ < 4; nj_++) {                   \
            ldsm4(bH_[nj_], bhp_ + (brow_ + nj_ * 16) * RSTR + bcol_);          \
        }                                                                       \
        _Pragma("unroll") for (int mi_ = 0; mi_ < 2; mi_++)                     \
        _Pragma("unroll") for (int ni_ = 0; ni_ < 8; ni_++) {                   \
            const uint32_t* bh2_ = &bH_[ni_ >> 1][(ni_ & 1) * 2];               \
            mma16816(acc[mi_][ni_], aH_[mi_], bh2_);                            \
        }                                                                       \
    }                                                                           \
} while (0)

    // prologue: fill buffers 0 and 1
    GLOAD(0); SSTORE(0);
    GLOAD(1); SSTORE(1);
    __syncthreads();
    // main loop: one barrier per two chunks
    for (int c = 0; c < nc; c += 2) {
        if (c + 2 < nc) { GLOAD(c + 2); }
        COMPUTE(c);
        if (c + 2 < nc) { SSTORE(c + 2); }
        if (c + 3 < nc) { GLOAD(c + 3); }
        COMPUTE(c + 1);
        if (c + 3 < nc) { SSTORE(c + 3); }
        __syncthreads();
    }

#pragma unroll
    for (int mi = 0; mi < 2; mi++) {
        const int r0 = bRow + wm * 32 + mi * 16 + (lane >> 2);
#pragma unroll
        for (int ni = 0; ni < 8; ni++) {
            const int col = bCol + wn * 64 + ni * 8 + (lane & 3) * 2;
            const float b0 = bias[col], b1 = bias[col + 1];
            if (r0 < M) {
                float c0 = acc[mi][ni][0] + b0, c1 = acc[mi][ni][1] + b1;
                if (RELU) { c0 = fmaxf(c0, 0.f); c1 = fmaxf(c1, 0.f); }
                if (C)  *(float2*)(C + (size_t)r0 * N + col) = make_float2(c0, c1);
                if (Ch) *(uint32_t*)(Ch + (size_t)r0 * N + col) = packh2(c0, c1);
            }
            if (r0 + 8 < M) {
                float c2 = acc[mi][ni][2] + b0, c3 = acc[mi][ni][3] + b1;
                if (RELU) { c2 = fmaxf(c2, 0.f); c3 = fmaxf(c3, 0.f); }
                if (C)  *(float2*)(C + (size_t)(r0 + 8) * N + col) = make_float2(c2, c3);
                if (Ch) *(uint32_t*)(Ch + (size_t)(r0 + 8) * N + col) = packh2(c2, c3);
            }
        }
    }
#undef GLOAD
#undef SSTORE
#undef COMPUTE
}

// ---------------- weight prep: W[K][N] fp32 -> T [N][K] fp16 ----------------
__global__ void k_wprep(const float* __restrict__ W, __half* __restrict__ Th,
                        int K, int N) {
    __shared__ float s[32][33];
    int n0 = blockIdx.x * 32, k0 = blockIdx.y * 32;
    for (int r = threadIdx.y; r < 32; r += 8)
        s[r][threadIdx.x] = W[(size_t)(k0 + r) * N + n0 + threadIdx.x];
    __syncthreads();
    for (int r = threadIdx.y; r < 32; r += 8) {
        float f = s[threadIdx.x][r];
        Th[(size_t)(n0 + r) * K + k0 + threadIdx.x] = __float2half_rn(f);
    }
}

// ---------------- fp32 -> fp16 elementwise (8 per thread) ----------------
__global__ void k_tohalf(const float* __restrict__ x, __half* __restrict__ y, unsigned n8) {
    unsigned i = blockIdx.x * blockDim.x + threadIdx.x;
    if (i >= n8) return;
    const float4* xp = (const float4*)(x) + 2 * (size_t)i;
    float4 a = xp[0], b = xp[1];
    uint4 o;
    o.x = packh2(a.x, a.y); o.y = packh2(a.z, a.w);
    o.z = packh2(b.x, b.y); o.w = packh2(b.z, b.w);
    ((uint4*)y)[i] = o;
}

// ---------------- CSR build ----------------
__global__ void k_zeroi(int* __restrict__ p, unsigned n) {
    unsigned i = blockIdx.x * blockDim.x + threadIdx.x;
    if (i < n) p[i] = 0;
}
__global__ void k_count(const int* __restrict__ dst, int* __restrict__ cnt) {
    unsigned e = blockIdx.x * blockDim.x + threadIdx.x;
    if (e >= TT * EE) return;
    int t = e / EE;
    atomicAdd(&cnt[t * NN + dst[e]], 1);
}
__global__ void k_scan(const int* __restrict__ cnt, int* __restrict__ rowptr,
                       int* __restrict__ cursor) {
    int t = blockIdx.x;
    __shared__ int sdata[1024];
    __shared__ int carry_s;
    if (threadIdx.x == 0) carry_s = t * EE;
    __syncthreads();
    for (int c0 = 0; c0 < NN; c0 += 1024) {
        int i = c0 + threadIdx.x;
        int v = (i < NN) ? cnt[t * NN + i] : 0;
        sdata[threadIdx.x] = v;
        __syncthreads();
        for (int off = 1; off < 1024; off <<= 1) {
            int add = (threadIdx.x >= (unsigned)off) ? sdata[threadIdx.x - off] : 0;
            __syncthreads();
            sdata[threadIdx.x] += add;
            __syncthreads();
        }
        int excl = sdata[threadIdx.x] - v;
        if (i < NN) {
            int r = carry_s + excl;
            rowptr[t * NN + i] = r;
            cursor[t * NN + i] = r;
        }
        __syncthreads();
        if (threadIdx.x == 0) carry_s += sdata[1023];
        __syncthreads();
    }
}
__global__ void k_fill(const int* __restrict__ src, const int* __restrict__ dst,
                       int* __restrict__ cursor, int* __restrict__ eidx) {
    unsigned e = blockIdx.x * blockDim.x + threadIdx.x;
    if (e >= TT * EE) return;
    int t = e / EE;
    int pos = atomicAdd(&cursor[t * NN + dst[e]], 1);
    eidx[pos] = t * NN + src[e];
}
// CSR mean-aggregate fp16 in (F=128 halfs), fp32 accum+out; lane loads uint2 (4 halfs)
__global__ void k_aggh128(const __half* __restrict__ x, const int* __restrict__ rowptr,
                          const int* __restrict__ cnt, const int* __restrict__ eidx,
                          float* __restrict__ agg) {
    int w = threadIdx.x >> 5, lane = threadIdx.x & 31;
    unsigned n = blockIdx.x * 8 + w;
    if (n >= MB) return;
    int beg = rowptr[n], c = cnt[n];
    float acc[4];
#pragma unroll
    for (int j = 0; j < 4; j++) acc[j] = 0.f;
    int i = 0;
    for (; i + 1 < c; i += 2) {
        int s0 = eidx[beg + i], s1 = eidx[beg + i + 1];
        uint2 v0 = *(const uint2*)(x + (size_t)s0 * DIN + lane * 4);
        uint2 v1 = *(const uint2*)(x + (size_t)s1 * DIN + lane * 4);
        const __half2* h0 = (const __half2*)&v0;
        const __half2* h1 = (const __half2*)&v1;
#pragma unroll
        for (int j = 0; j < 2; j++) {
            float2 a = __half22float2(h0[j]), b = __half22float2(h1[j]);
            acc[2*j]   += a.x + b.x;
            acc[2*j+1] += a.y + b.y;
        }
    }
    if (i < c) {
        uint2 v0 = *(const uint2*)(x + (size_t)eidx[beg + i] * DIN + lane * 4);
        const __half2* h0 = (const __half2*)&v0;
#pragma unroll
        for (int j = 0; j < 2; j++) {
            float2 a = __half22float2(h0[j]);
            acc[2*j]   += a.x;
            acc[2*j+1] += a.y;
        }
    }
    float sc = 1.0f / (float)(c > 0 ? c : 1);
    ((float4*)(agg + (size_t)n * DIN + lane * 4))[0] =
        make_float4(acc[0]*sc, acc[1]*sc, acc[2]*sc, acc[3]*sc);
}
// CSR mean-aggregate fp16 in (F=256 halfs), fp32 accum+out; lane loads uint4 (8 halfs)
__global__ void k_aggh256(const __half* __restrict__ x, const int* __restrict__ rowptr,
                          const int* __restrict__ cnt, const int* __restrict__ eidx,
                          float* __restrict__ agg) {
    int w = threadIdx.x >> 5, lane = threadIdx.x & 31;
    unsigned n = blockIdx.x * 8 + w;
    if (n >= MB) return;
    int beg = rowptr[n], c = cnt[n];
    float acc[8];
#pragma unroll
    for (int j = 0; j < 8; j++) acc[j] = 0.f;
    int i = 0;
    for (; i + 1 < c; i += 2) {
        int s0 = eidx[beg + i], s1 = eidx[beg + i + 1];
        uint4 v0 = *(const uint4*)(x + (size_t)s0 * 256 + lane * 8);
        uint4 v1 = *(const uint4*)(x + (size_t)s1 * 256 + lane * 8);
        const __half2* h0 = (const __half2*)&v0;
        const __half2* h1 = (const __half2*)&v1;
#pragma unroll
        for (int j = 0; j < 4; j++) {
            float2 a = __half22float2(h0[j]), b = __half22float2(h1[j]);
            acc[2*j]   += a.x + b.x;
            acc[2*j+1] += a.y + b.y;
        }
    }
    if (i < c) {
        uint4 v0 = *(const uint4*)(x + (size_t)eidx[beg + i] * 256 + lane * 8);
        const __half2* h0 = (const __half2*)&v0;
#pragma unroll
        for (int j = 0; j < 4; j++) {
            float2 a = __half22float2(h0[j]);
            acc[2*j]   += a.x;
            acc[2*j+1] += a.y;
        }
    }
    float sc = 1.0f / (float)(c > 0 ? c : 1);
    float* dst = agg + (size_t)n * 256 + lane * 8;
    ((float4*)dst)[0] = make_float4(acc[0]*sc, acc[1]*sc, acc[2]*sc, acc[3]*sc);
    ((float4*)dst)[1] = make_float4(acc[4]*sc, acc[5]*sc, acc[6]*sc, acc[7]*sc);
}

// ---------------- misc kernels ----------------
// fused L2-norm + gather; writes fp32 att_out, fp32 residual h, fp16 h16
__global__ void k_normgather(const float* __restrict__ h2, const int* __restrict__ idx,
                             float* __restrict__ att_out, float* __restrict__ hbuf,
                             __half* __restrict__ h16, int off) {
    int w = threadIdx.x >> 5, lane = threadIdx.x & 31;
    unsigned tp = blockIdx.x * 8 + w;
    int t = tp >> 12, p = tp & 4095;
    int n = idx[t * PP + p];
    const float* row = h2 + ((size_t)t * NN + n) * HH;
    float v[8]; float ss = 0.f;
#pragma unroll
    for (int i = 0; i < 8; i++) { v[i] = row[lane + i * 32]; ss += v[i] * v[i]; }
#pragma unroll
    for (int o = 16; o; o >>= 1) ss += __shfl_xor_sync(0xffffffffu, ss, o);
    float inv = 1.0f / fmaxf(sqrtf(ss), 1e-12f);
    size_t o0 = (size_t)tp * DDm + off;
#pragma unroll
    for (int i = 0; i < 8; i++) {
        float val = v[i] * inv;
        att_out[o0 + lane + i * 32] = val;
        hbuf[o0 + lane + i * 32] = val;
        h16[o0 + lane + i * 32] = __float2half_rn(val);
    }
}
__global__ void k_attn(const __half* __restrict__ qkv, __half* __restrict__ oh) {
    int p = blockIdx.x, h = blockIdx.y;
    int tid = threadIdx.x;
    __shared__ float qs[TT][64], ks[TT][64], vs[TT][64];
    __shared__ float att[TT][4];
    size_t base = (size_t)p * 1536 + h * 64 + tid;
#pragma unroll
    for (int t = 0; t < TT; t++) {
        size_t off = (size_t)t * PP * 1536 + base;
        qs[t][tid] = __half2float(qkv[off]);
        ks[t][tid] = __half2float(qkv[off + 512]);
        vs[t][tid] = __half2float(qkv[off + 1024]);
    }
    __syncthreads();
    {
        int t = tid >> 2, j = tid & 3, s = t - j;
        float sc = -INFINITY;
        if (s >= 0) {
            float a = 0.f;
#pragma unroll
            for (int d = 0; d < 64; d++) a += qs[t][d] * ks[s][d];
            sc = a * 0.125f;
        }
        att[t][j] = sc;
    }
    __syncthreads();
    if (tid < TT) {
        float m = -INFINITY;
#pragma unroll
        for (int j = 0; j < 4; j++) m = fmaxf(m, att[tid][j]);
        float sum = 0.f, e[4];
#pragma unroll
        for (int j = 0; j < 4; j++) {
            float x = att[tid][j];
            float ee = (x == -INFINITY) ? 0.f : expf(x - m);
            e[j] = ee; sum += ee;
        }
        float inv = 1.0f / sum;
#pragma unroll
        for (int j = 0; j < 4; j++) att[tid][j] = e[j] * inv;
    }
    __syncthreads();
    size_t obase = (size_t)p * DDm + h * 64 + tid;
#pragma unroll
    for (int t = 0; t < TT; t++) {
        float a = 0.f;
#pragma unroll
        for (int j = 0; j < 4; j++) {
            int s = t - j;
            if (s >= 0) a += att[t][j] * vs[s][tid];
        }
        oh[(size_t)t * PP * DDm + obase] = __float2half_rn(a);
    }
}
// LN: h = LN(h + r)*g + b; also writes fp16 copy
__global__ void k_ln(const float* __restrict__ r, const float* __restrict__ g,
                     const float* __restrict__ b, __half* __restrict__ h16) {
    int w = threadIdx.x >> 5, lane = threadIdx.x & 31;
    size_t row = (size_t)blockIdx.x * 8 + w;
    float* xr = g_h + row * DDm;
    const float* rr = r + row * DDm;
    float v[16]; float s = 0.f;
#pragma unroll
    for (int i = 0; i < 16; i++) {
        int c = lane + i * 32;
        float t = xr[c] + rr[c];
        v[i] = t; s += t;
    }
#pragma unroll
    for (int o = 16; o; o >>= 1) s += __shfl_xor_sync(0xffffffffu, s, o);
    float mean = s * (1.0f / DDm);
    float vs = 0.f;
#pragma unroll
    for (int i = 0; i < 16; i++) { float d = v[i] - mean; vs += d * d; }
#pragma unroll
    for (int o = 16; o; o >>= 1) vs += __shfl_xor_sync(0xffffffffu, vs, o);
    float inv = rsqrtf(vs * (1.0f / DDm) + 1e-5f);
#pragma unroll
    for (int i = 0; i < 16; i++) {
        int c = lane + i * 32;
        float val = (v[i] - mean) * inv * g[c] + b[c];
        xr[c] = val;
        h16[row * DDm + c] = __float2half_rn(val);
    }
}
__global__ void k_out(const float* __restrict__ wout, float* __restrict__ out) {
    int w = threadIdx.x >> 5, lane = threadIdx.x & 31;
    size_t row = (size_t)blockIdx.x * 8 + w;
    const float* hr = g_h + row * DDm;
    float s = 0.f;
#pragma unroll
    for (int i = 0; i < 16; i++) { int c = lane + i * 32; s += hr[c] * wout[c]; }
#pragma unroll
    for (int o = 16; o; o >>= 1) s += __shfl_xor_sync(0xffffffffu, s, o);
    if (lane == 0) out[row] = s;
}

// =======================================================================================
extern "C" void kernel_launch(void* const* d_in, const int* in_sizes, int n_in,
                              void* d_out, int out_size) {
    const float* x_i  = (const float*)d_in[0];
    const float* x_j  = (const float*)d_in[1];
    const int* src_i  = (const int*)d_in[2];
    const int* dst_i  = (const int*)d_in[3];
    const int* src_j  = (const int*)d_in[4];
    const int* dst_j  = (const int*)d_in[5];
    const int* idx_i  = (const int*)d_in[6];
    const int* idx_j  = (const int*)d_in[7];
    const float* W1s  = (const float*)d_in[8];
    const float* W1n  = (const float*)d_in[9];
    const float* b1   = (const float*)d_in[10];
    const float* W2s  = (const float*)d_in[11];
    const float* W2n  = (const float*)d_in[12];
    const float* b2   = (const float*)d_in[13];
    const float* Wq   = (const float*)d_in[14];
    const float* Wk   = (const float*)d_in[15];
    const float* Wv   = (const float*)d_in[16];
    const float* bq   = (const float*)d_in[17];
    const float* bk   = (const float*)d_in[18];
    const float* bv   = (const float*)d_in[19];
    const float* Wo   = (const float*)d_in[20];
    const float* bo   = (const float*)d_in[21];
    const float* Wf1  = (const float*)d_in[22];
    const float* bf1  = (const float*)d_in[23];
    const float* Wf2  = (const float*)d_in[24];
    const float* bf2  = (const float*)d_in[25];
    const float* g1   = (const float*)d_in[26];
    const float* bg1  = (const float*)d_in[27];
    const float* g2   = (const float*)d_in[28];
    const float* bg2  = (const float*)d_in[29];
    const float* Wout = (const float*)d_in[30];
    float* out = (float*)d_out;

    float *p_aggB, *p_h2B, *p_h, *p_proj, *p_bqkv;
    __half *p_xh, *p_h1h, *p_h16, *p_qkvh, *p_oh, *p_ffh;
    int *p_cnt, *p_rowptr, *p_cursor, *p_eidx;
    __half* p_w;
    cudaGetSymbolAddress((void**)&p_cnt,    g_cnt);
    cudaGetSymbolAddress((void**)&p_rowptr, g_rowptr);
    cudaGetSymbolAddress((void**)&p_cursor, g_cursor);
    cudaGetSymbolAddress((void**)&p_eidx,   g_eidx);
    cudaGetSymbolAddress((void**)&p_xh,     g_xh);
    cudaGetSymbolAddress((void**)&p_aggB,   g_aggB);
    cudaGetSymbolAddress((void**)&p_h1h,    g_h1h);
    cudaGetSymbolAddress((void**)&p_h2B,    g_h2B);
    cudaGetSymbolAddress((void**)&p_h,      g_h);
    cudaGetSymbolAddress((void**)&p_h16,    g_h16);
    cudaGetSymbolAddress((void**)&p_qkvh,   g_qkvh);
    cudaGetSymbolAddress((void**)&p_oh,     g_oh);
    cudaGetSymbolAddress((void**)&p_ffh,    g_ffh);
    cudaGetSymbolAddress((void**)&p_proj,   g_proj);
    cudaGetSymbolAddress((void**)&p_bqkv,   g_bqkv);
    cudaGetSymbolAddress((void**)&p_w,      g_w);

    cudaFuncSetAttribute(gemm_mma<true >, cudaFuncAttributeMaxDynamicSharedMemorySize, GSMEM);
    cudaFuncSetAttribute(gemm_mma<false>, cudaFuncAttributeMaxDynamicSharedMemorySize, GSMEM);

    // ---- stream fork (capture-safe: event fork off the capturing default stream) ----
    cudaStream_t s1;
    cudaStreamCreate(&s1);
    cudaEvent_t evF, evW, evJ;
    cudaEventCreateWithFlags(&evF, cudaEventDisableTiming);
    cudaEventCreateWithFlags(&evW, cudaEventDisableTiming);
    cudaEventCreateWithFlags(&evJ, cudaEventDisableTiming);
    cudaEventRecord(evF, 0);
    cudaStreamWaitEvent(s1, evF, 0);

    // ---- weight prep on default stream ----
    size_t off = 0;
    auto prep = [&](const float* W, int K, int N) -> size_t {
        size_t b = off;
        k_wprep<<<dim3(N/32, K/32), dim3(32, 8)>>>(W, p_w + b, K, N);
        off += (size_t)K * N;
        return b;
    };
    size_t oW1s = prep(W1s, DIN, HH), oW1n = prep(W1n, DIN, HH);
    size_t oW2s = prep(W2s, HH, HH),  oW2n = prep(W2n, HH, HH);
    cudaEventRecord(evW, 0);   // SAGE weights ready

    size_t oQKV[2];
    for (int l = 0; l < 2; l++) {
        size_t b = off; off += (size_t)1536 * DDm;
        const size_t KN = (size_t)DDm * DDm;
        k_wprep<<<dim3(DDm/32, DDm/32), dim3(32, 8)>>>(Wq + (size_t)l*KN, p_w + b,        DDm, DDm);
        k_wprep<<<dim3(DDm/32, DDm/32), dim3(32, 8)>>>(Wk + (size_t)l*KN, p_w + b + KN,   DDm, DDm);
        k_wprep<<<dim3(DDm/32, DDm/32), dim3(32, 8)>>>(Wv + (size_t)l*KN, p_w + b + 2*KN, DDm, DDm);
        oQKV[l] = b;
    }
    size_t oWo[2], oWf1[2], oWf2[2];
    for (int l = 0; l < 2; l++) {
        oWo[l]  = prep(Wo  + (size_t)l*DDm*DDm, DDm, DDm);
        oWf1[l] = prep(Wf1 + (size_t)l*DDm*FFD, DDm, FFD);
        oWf2[l] = prep(Wf2 + (size_t)l*FFD*DDm, FFD, DDm);
    }
    auto BH = [&](size_t b) { return p_w + b; };

    for (int l = 0; l < 2; l++) {
        cudaMemcpyAsync(p_bqkv + l*1536,        bq + l*DDm, DDm*4, cudaMemcpyDeviceToDevice);
        cudaMemcpyAsync(p_bqkv + l*1536 + 512,  bk + l*DDm, DDm*4, cudaMemcpyDeviceToDevice);
        cudaMemcpyAsync(p_bqkv + l*1536 + 1024, bv + l*DDm, DDm*4, cudaMemcpyDeviceToDevice);
    }

    // ---------- GraphSAGE: two independent graph pipelines on two streams ----------
    for (int gsel = 0; gsel < 2; gsel++) {
        cudaStream_t st = gsel ? s1 : (cudaStream_t)0;
        const float* x  = gsel ? x_j   : x_i;
        const int* src  = gsel ? src_j : src_i;
        const int* dstp = gsel ? dst_j : dst_i;
        const int* idx  = gsel ? idx_j : idx_i;
        int*   cnt    = p_cnt    + (size_t)gsel * MB;
        int*   rowptr = p_rowptr + (size_t)gsel * MB;
        int*   cursor = p_cursor + (size_t)gsel * MB;
        int*   eidx   = p_eidx   + (size_t)gsel * TT * EE;
        __half* xh    = p_xh     + (size_t)gsel * MB * DIN;
        float* aggB   = p_aggB   + (size_t)gsel * MB * HH;
        __half* h1h   = p_h1h    + (size_t)gsel * MB * HH;
        float* h2B    = p_h2B    + (size_t)gsel * MB * HH;

        k_zeroi <<<(MB + 255)/256, 256, 0, st>>>(cnt, MB);
        k_count <<<(TT*EE + 255)/256, 256, 0, st>>>(dstp, cnt);
        k_scan  <<<TT, 1024, 0, st>>>(cnt, rowptr, cursor);
        k_fill  <<<(TT*EE + 255)/256, 256, 0, st>>>(src, dstp, cursor, eidx);
        k_tohalf<<<((unsigned)(MB*DIN/8) + 255)/256, 256, 0, st>>>(x, xh, (unsigned)(MB*DIN/8));
        k_aggh128<<<(MB + 7)/8, 256, 0, st>>>(xh, rowptr, cnt, eidx, aggB);

        if (gsel == 1) cudaStreamWaitEvent(st, evW, 0);

        // layer 1: fp16 x direct + fp32 agg; emits fp16 h1 only
        gemm_mma<true><<<dim3(HH/128, (MB + 127)/128), 256, GSMEM, st>>>(
            xh, BH(oW1s), DIN, aggB, BH(oW1n), DIN, b1, nullptr, h1h, MB, HH);

        // layer 2: fp16 gather-mean, fp16 A direct + fp32 agg
        k_aggh256<<<(MB + 7)/8, 256, 0, st>>>(h1h, rowptr, cnt, eidx, aggB);
        gemm_mma<false><<<dim3(HH/128, (MB + 127)/128), 256, GSMEM, st>>>(
            h1h, BH(oW2s), HH, aggB, BH(oW2n), HH, b2, h2B, nullptr, MB, HH);

        k_normgather<<<TPR/8, 256, 0, st>>>(h2B, idx, out, p_h, p_h16, gsel * HH);
    }
    cudaEventRecord(evJ, s1);
    cudaStreamWaitEvent(0, evJ, 0);

    // ---------- transformer (L=2) ----------
    for (int l = 0; l < 2; l++) {
        // QKV: fp16 A (h16), fp16 output
        gemm_mma<false><<<dim3(1536/128, TPR/128), 256, GSMEM>>>(
            p_h16, BH(oQKV[l]), DDm, nullptr, nullptr, 0,
            p_bqkv + l*1536, nullptr, p_qkvh, TPR, 1536);

        k_attn<<<dim3(PP, 8), 64>>>(p_qkvh, p_oh);

        gemm_mma<false><<<dim3(DDm/128, TPR/128), 256, GSMEM>>>(
            p_oh, BH(oWo[l]), DDm, nullptr, nullptr, 0,
            bo + l*DDm, p_proj, nullptr, TPR, DDm);
        k_ln<<<TPR/8, 256>>>(p_proj, g1 + l*DDm, bg1 + l*DDm, p_h16);

        // FF1: fp16 A (h16), fp16 output
        gemm_mma<true><<<dim3(FFD/128, TPR/128), 256, GSMEM>>>(
            p_h16, BH(oWf1[l]), DDm, nullptr, nullptr, 0,
            bf1 + l*FFD, nullptr, p_ffh, TPR, FFD);
        gemm_mma<false><<<dim3(DDm/128, TPR/128), 256, GSMEM>>>(
            p_ffh, BH(oWf2[l]), FFD, nullptr, nullptr, 0,
            bf2 + l*DDm, p_proj, nullptr, TPR, DDm);
        k_ln<<<TPR/8, 256>>>(p_proj, g2 + l*DDm, bg2 + l*DDm, p_h16);
    }

    k_out<<<TPR/8, 256>>>(Wout, out + (size_t)TPR * DDm);
}